// round 2
// baseline (speedup 1.0000x reference)
#include <cuda_runtime.h>
#include <cuda_bf16.h>
#include <math.h>

#define B_BATCH 4
#define S_LEN   4096
#define D_MODEL 512
#define HALF_W  128
#define BAND    320   // per 64-query tile: 64 + 2*128
#define NTILES  (S_LEN / 64)   // 64 query tiles per batch

// ---------------- device scratch (no allocations allowed) ----------------
__device__ float g_Q[(size_t)B_BATCH * S_LEN * D_MODEL];
__device__ float g_K[(size_t)B_BATCH * S_LEN * D_MODEL];
__device__ float g_V[(size_t)B_BATCH * S_LEN * D_MODEL];
// P stored tile-aligned: [B][tile][64 rows][320 cols], zero outside each row's band
__device__ float g_P[(size_t)B_BATCH * NTILES * 64 * BAND];

// =====================================================================
// Kernel 1: QKV projection. out = x @ W + b for z = 0,1,2 (Q,K,V)
// 128x128 block tile, BK=16, 256 threads, 8x8 micro-tile.
// =====================================================================
__global__ __launch_bounds__(256) void qkv_gemm(
    const float* __restrict__ x,
    const float* __restrict__ Wq, const float* __restrict__ Wk, const float* __restrict__ Wv,
    const float* __restrict__ bq, const float* __restrict__ bk, const float* __restrict__ bv)
{
    const float* W;
    const float* bias;
    float* out;
    if (blockIdx.z == 0)      { W = Wq; bias = bq; out = g_Q; }
    else if (blockIdx.z == 1) { W = Wk; bias = bk; out = g_K; }
    else                      { W = Wv; bias = bv; out = g_V; }

    __shared__ float As[16][132];   // transposed A tile: As[k][m]
    __shared__ float Bs[16][128];   // B tile: Bs[k][n]

    const int m0 = blockIdx.y * 128;
    const int n0 = blockIdx.x * 128;
    const int tid = threadIdx.x;
    const int tx = tid & 15;        // 0..15  -> col base tx*8
    const int ty = tid >> 4;        // 0..15  -> row base ty*8

    float acc[8][8];
#pragma unroll
    for (int i = 0; i < 8; i++)
#pragma unroll
        for (int j = 0; j < 8; j++) acc[i][j] = 0.f;

    for (int kb = 0; kb < D_MODEL; kb += 16) {
        // load A tile 128x16 (512 float4, 2 per thread), store transposed
#pragma unroll
        for (int i = 0; i < 2; i++) {
            int idx = i * 256 + tid;          // 0..511
            int row = idx >> 2;               // 0..127
            int k4  = idx & 3;                // 0..3
            float4 v = *(const float4*)&x[(size_t)(m0 + row) * D_MODEL + kb + k4 * 4];
            As[k4 * 4 + 0][row] = v.x;
            As[k4 * 4 + 1][row] = v.y;
            As[k4 * 4 + 2][row] = v.z;
            As[k4 * 4 + 3][row] = v.w;
        }
        // load B tile 16x128 (512 float4, 2 per thread), direct
#pragma unroll
        for (int i = 0; i < 2; i++) {
            int idx = i * 256 + tid;
            int row = idx >> 5;               // 0..15
            int c4  = idx & 31;               // 0..31
            *(float4*)&Bs[row][c4 * 4] =
                *(const float4*)&W[(size_t)(kb + row) * D_MODEL + n0 + c4 * 4];
        }
        __syncthreads();

#pragma unroll
        for (int k = 0; k < 16; k++) {
            float a[8], b[8];
            *(float4*)&a[0] = *(float4*)&As[k][ty * 8];
            *(float4*)&a[4] = *(float4*)&As[k][ty * 8 + 4];
            *(float4*)&b[0] = *(float4*)&Bs[k][tx * 8];
            *(float4*)&b[4] = *(float4*)&Bs[k][tx * 8 + 4];
#pragma unroll
            for (int i = 0; i < 8; i++)
#pragma unroll
                for (int j = 0; j < 8; j++)
                    acc[i][j] = fmaf(a[i], b[j], acc[i][j]);
        }
        __syncthreads();
    }

    // epilogue: add bias, store
#pragma unroll
    for (int i = 0; i < 8; i++) {
        size_t row = (size_t)(m0 + ty * 8 + i);
#pragma unroll
        for (int j = 0; j < 8; j += 4) {
            int n = n0 + tx * 8 + j;
            float4 o;
            o.x = acc[i][j + 0] + bias[n + 0];
            o.y = acc[i][j + 1] + bias[n + 1];
            o.z = acc[i][j + 2] + bias[n + 2];
            o.w = acc[i][j + 3] + bias[n + 3];
            *(float4*)&out[row * D_MODEL + n] = o;
        }
    }
}

// =====================================================================
// Kernel 2: banded scores + softmax -> P
// Block = 64 queries x 320 keys (full band of the tile), K-dim 512.
// 256 threads as 16x16; each thread owns 4 rows x 20 cols (5 key sub-tiles).
// Softmax across the 16 lanes sharing a row via width-16 shuffles.
// =====================================================================
__global__ __launch_bounds__(256) void attn_scores()
{
    const int t0 = blockIdx.x * 64;      // query tile start
    const int b  = blockIdx.y;
    const float* Q = g_Q + (size_t)b * S_LEN * D_MODEL;
    const float* K = g_K + (size_t)b * S_LEN * D_MODEL;
    float* P = g_P + ((size_t)(b * NTILES + blockIdx.x)) * 64 * BAND;

    __shared__ float As[16][64];     // As[k][q-row]
    __shared__ float Bs[16][BAND];   // Bs[k][key-col]

    const int tid = threadIdx.x;
    const int tx = tid & 15;
    const int ty = tid >> 4;

    float acc[4][20];
#pragma unroll
    for (int i = 0; i < 4; i++)
#pragma unroll
        for (int c = 0; c < 20; c++) acc[i][c] = 0.f;

    for (int kb = 0; kb < D_MODEL; kb += 16) {
        // Q tile: 64x16 = 256 float4, 1 per thread, transposed store
        {
            int row = tid >> 2;              // 0..63
            int k4  = tid & 3;
            float4 v = *(const float4*)&Q[(size_t)(t0 + row) * D_MODEL + kb + k4 * 4];
            As[k4 * 4 + 0][row] = v.x;
            As[k4 * 4 + 1][row] = v.y;
            As[k4 * 4 + 2][row] = v.z;
            As[k4 * 4 + 3][row] = v.w;
        }
        // K tile: 320x16 = 1280 float4, 5 per thread, transposed store, OOB->0
#pragma unroll
        for (int i = 0; i < 5; i++) {
            int idx = i * 256 + tid;         // 0..1279
            int row = idx >> 2;              // 0..319
            int k4  = idx & 3;
            int jg = t0 - HALF_W + row;
            float4 v = make_float4(0.f, 0.f, 0.f, 0.f);
            if (jg >= 0 && jg < S_LEN)
                v = *(const float4*)&K[(size_t)jg * D_MODEL + kb + k4 * 4];
            Bs[k4 * 4 + 0][row] = v.x;
            Bs[k4 * 4 + 1][row] = v.y;
            Bs[k4 * 4 + 2][row] = v.z;
            Bs[k4 * 4 + 3][row] = v.w;
        }
        __syncthreads();

#pragma unroll
        for (int k = 0; k < 16; k++) {
            float a[4];
            *(float4*)&a[0] = *(float4*)&As[k][ty * 4];
#pragma unroll
            for (int kt = 0; kt < 5; kt++) {
                float4 bv = *(float4*)&Bs[k][kt * 64 + tx * 4];
#pragma unroll
                for (int i = 0; i < 4; i++) {
                    acc[i][kt * 4 + 0] = fmaf(a[i], bv.x, acc[i][kt * 4 + 0]);
                    acc[i][kt * 4 + 1] = fmaf(a[i], bv.y, acc[i][kt * 4 + 1]);
                    acc[i][kt * 4 + 2] = fmaf(a[i], bv.z, acc[i][kt * 4 + 2]);
                    acc[i][kt * 4 + 3] = fmaf(a[i], bv.w, acc[i][kt * 4 + 3]);
                }
            }
        }
        __syncthreads();
    }

    const float scale = 0.044194173824159216f;  // 1/sqrt(512)

#pragma unroll
    for (int i = 0; i < 4; i++) {
        const int r = ty * 4 + i;                // row within tile
        float m = -INFINITY;
#pragma unroll
        for (int c = 0; c < 20; c++) {
            int col = (c >> 2) * 64 + tx * 4 + (c & 3);
            int jg = t0 - HALF_W + col;
            bool valid = (col >= r) && (col <= r + 2 * HALF_W) && (jg >= 0) && (jg < S_LEN);
            float v = valid ? acc[i][c] * scale : -INFINITY;
            acc[i][c] = v;
            m = fmaxf(m, v);
        }
#pragma unroll
        for (int off = 8; off; off >>= 1)
            m = fmaxf(m, __shfl_xor_sync(0xffffffffu, m, off, 16));

        float sum = 0.f;
#pragma unroll
        for (int c = 0; c < 20; c++) {
            float e = __expf(acc[i][c] - m);     // exp(-inf - m) = 0 for masked
            acc[i][c] = e;
            sum += e;
        }
#pragma unroll
        for (int off = 8; off; off >>= 1)
            sum += __shfl_xor_sync(0xffffffffu, sum, off, 16);

        float inv = 1.0f / sum;
#pragma unroll
        for (int kt = 0; kt < 5; kt++) {
            float4 o;
            o.x = acc[i][kt * 4 + 0] * inv;
            o.y = acc[i][kt * 4 + 1] * inv;
            o.z = acc[i][kt * 4 + 2] * inv;
            o.w = acc[i][kt * 4 + 3] * inv;
            *(float4*)&P[(size_t)r * BAND + kt * 64 + tx * 4] = o;
        }
    }
}

// =====================================================================
// Kernel 3: O = P @ V_band  (dense GEMM per tile: [64 x 320] @ [320 x 512])
// 64x128 block tile, BK=16, 256 threads, 4x8 micro-tile.
// V rows clamped at sequence edges (P is exactly 0 there).
// =====================================================================
__global__ __launch_bounds__(256) void attn_out(float* __restrict__ out)
{
    const int n0   = blockIdx.x * 128;
    const int tile = blockIdx.y;
    const int b    = blockIdx.z;
    const int t0   = tile * 64;

    const float* P = g_P + ((size_t)(b * NTILES + tile)) * 64 * BAND;
    const float* V = g_V + (size_t)b * S_LEN * D_MODEL;

    __shared__ float As[16][64];    // As[k][q-row]
    __shared__ float Bs[16][128];   // Bs[k][n]

    const int tid = threadIdx.x;
    const int tx = tid & 15;        // col base tx*8
    const int ty = tid >> 4;        // row base ty*4

    float acc[4][8];
#pragma unroll
    for (int i = 0; i < 4; i++)
#pragma unroll
        for (int j = 0; j < 8; j++) acc[i][j] = 0.f;

    for (int kb = 0; kb < BAND; kb += 16) {
        // P tile 64x16 = 256 float4, 1 per thread, transposed store
        {
            int row = tid >> 2;
            int k4  = tid & 3;
            float4 v = *(const float4*)&P[(size_t)row * BAND + kb + k4 * 4];
            As[k4 * 4 + 0][row] = v.x;
            As[k4 * 4 + 1][row] = v.y;
            As[k4 * 4 + 2][row] = v.z;
            As[k4 * 4 + 3][row] = v.w;
        }
        // V tile 16x128 (16 band rows x 128 cols) = 512 float4, 2 per thread
#pragma unroll
        for (int i = 0; i < 2; i++) {
            int idx = i * 256 + tid;
            int kr = idx >> 5;     // 0..15
            int c4 = idx & 31;     // 0..31
            int jg = t0 - HALF_W + kb + kr;
            jg = max(0, min(S_LEN - 1, jg));   // clamp; P==0 for OOB cols
            *(float4*)&Bs[kr][c4 * 4] =
                *(const float4*)&V[(size_t)jg * D_MODEL + n0 + c4 * 4];
        }
        __syncthreads();

#pragma unroll
        for (int k = 0; k < 16; k++) {
            float a[4], bb[8];
            *(float4*)&a[0]  = *(float4*)&As[k][ty * 4];
            *(float4*)&bb[0] = *(float4*)&Bs[k][tx * 8];
            *(float4*)&bb[4] = *(float4*)&Bs[k][tx * 8 + 4];
#pragma unroll
            for (int i = 0; i < 4; i++)
#pragma unroll
                for (int j = 0; j < 8; j++)
                    acc[i][j] = fmaf(a[i], bb[j], acc[i][j]);
        }
        __syncthreads();
    }

#pragma unroll
    for (int i = 0; i < 4; i++) {
        size_t row = (size_t)b * S_LEN + t0 + ty * 4 + i;
#pragma unroll
        for (int j = 0; j < 8; j += 4) {
            float4 o;
            o.x = acc[i][j + 0]; o.y = acc[i][j + 1];
            o.z = acc[i][j + 2]; o.w = acc[i][j + 3];
            *(float4*)&out[row * D_MODEL + n0 + tx * 8 + j] = o;
        }
    }
}

// =====================================================================
extern "C" void kernel_launch(void* const* d_in, const int* in_sizes, int n_in,
                              void* d_out, int out_size)
{
    const float* x  = (const float*)d_in[0];
    const float* Wq = (const float*)d_in[1];
    const float* bq = (const float*)d_in[2];
    const float* Wk = (const float*)d_in[3];
    const float* bk = (const float*)d_in[4];
    const float* Wv = (const float*)d_in[5];
    const float* bv = (const float*)d_in[6];
    float* out = (float*)d_out;

    // 1) QKV projections: grid (N/128, M/128, 3)
    qkv_gemm<<<dim3(D_MODEL / 128, (B_BATCH * S_LEN) / 128, 3), 256>>>(
        x, Wq, Wk, Wv, bq, bk, bv);

    // 2) banded scores + softmax
    attn_scores<<<dim3(NTILES, B_BATCH), 256>>>();

    // 3) O = P @ V
    attn_out<<<dim3(D_MODEL / 128, NTILES, B_BATCH), 256>>>(out);
}

// round 3
// speedup vs baseline: 2.4542x; 2.4542x over previous
#include <cuda_runtime.h>
#include <math.h>

#define B_BATCH 4
#define S_LEN   4096
#define D_MODEL 512
#define HALF_W  128
#define BAND    320
#define NTILES  (S_LEN / 64)

// ---------------- device scratch (no allocations allowed) ----------------
__device__ float g_Q[(size_t)B_BATCH * S_LEN * D_MODEL];
__device__ float g_K[(size_t)B_BATCH * S_LEN * D_MODEL];
__device__ float g_V[(size_t)B_BATCH * S_LEN * D_MODEL];
// P tile-aligned: [B][tile][64 rows][320 cols], zero outside each row's band
__device__ float g_P[(size_t)B_BATCH * NTILES * 64 * BAND];

// ---------------- helpers ----------------
__device__ __forceinline__ unsigned f2tf(float f) {
    unsigned r;
    asm("cvt.rna.tf32.f32 %0, %1;" : "=r"(r) : "f"(f));
    return r;
}

__device__ __forceinline__ void mma_tf32(float c[4],
                                         unsigned a0, unsigned a1, unsigned a2, unsigned a3,
                                         unsigned b0, unsigned b1) {
    asm volatile(
        "mma.sync.aligned.m16n8k8.row.col.f32.tf32.tf32.f32 "
        "{%0,%1,%2,%3}, {%4,%5,%6,%7}, {%8,%9}, {%0,%1,%2,%3};\n"
        : "+f"(c[0]), "+f"(c[1]), "+f"(c[2]), "+f"(c[3])
        : "r"(a0), "r"(a1), "r"(a2), "r"(a3), "r"(b0), "r"(b1));
}

// =====================================================================
// Kernel 1: QKV projection via tf32 MMA.
// Block tile 128x128, Ktile 32, 256 threads (8 warps as 2m x 4n),
// warp tile 64x32 -> 4 m-frags x 4 n-frags.
// =====================================================================
__global__ __launch_bounds__(256) void qkv_mma(
    const float* __restrict__ x,
    const float* __restrict__ Wq, const float* __restrict__ Wk, const float* __restrict__ Wv,
    const float* __restrict__ bq, const float* __restrict__ bk, const float* __restrict__ bv)
{
    const float* W;
    const float* bias;
    float* out;
    if (blockIdx.z == 0)      { W = Wq; bias = bq; out = g_Q; }
    else if (blockIdx.z == 1) { W = Wk; bias = bk; out = g_K; }
    else                      { W = Wv; bias = bv; out = g_V; }

    __shared__ unsigned As[32][136];   // As[k][m], +8 pad -> conflict-free frag loads
    __shared__ unsigned Bs[32][136];   // Bs[k][n]

    const int m0 = blockIdx.y * 128;
    const int n0 = blockIdx.x * 128;
    const int tid = threadIdx.x;
    const int warp = tid >> 5;
    const int lane = tid & 31;
    const int warp_m = warp >> 2;       // 0..1
    const int warp_n = warp & 3;        // 0..3
    const int g  = lane >> 2;           // groupID 0..7
    const int tg = lane & 3;            // threadID_in_group 0..3

    float acc[4][4][4];
#pragma unroll
    for (int mf = 0; mf < 4; mf++)
#pragma unroll
        for (int nf = 0; nf < 4; nf++)
#pragma unroll
            for (int c = 0; c < 4; c++) acc[mf][nf][c] = 0.f;

    for (int kb = 0; kb < D_MODEL; kb += 32) {
        // A: 128x32 = 1024 float4, 4 per thread, transpose + cvt
#pragma unroll
        for (int i = 0; i < 4; i++) {
            int idx = i * 256 + tid;
            int row = idx >> 3;               // 0..127
            int k4  = idx & 7;                // 0..7
            float4 v = *(const float4*)&x[(size_t)(m0 + row) * D_MODEL + kb + k4 * 4];
            As[k4 * 4 + 0][row] = f2tf(v.x);
            As[k4 * 4 + 1][row] = f2tf(v.y);
            As[k4 * 4 + 2][row] = f2tf(v.z);
            As[k4 * 4 + 3][row] = f2tf(v.w);
        }
        // B: 32x128 = 1024 float4, 4 per thread, direct + cvt
#pragma unroll
        for (int i = 0; i < 4; i++) {
            int idx = i * 256 + tid;
            int kr = idx >> 5;                // 0..31
            int c4 = idx & 31;                // 0..31
            float4 v = *(const float4*)&W[(size_t)(kb + kr) * D_MODEL + n0 + c4 * 4];
            uint4 u = make_uint4(f2tf(v.x), f2tf(v.y), f2tf(v.z), f2tf(v.w));
            *(uint4*)&Bs[kr][c4 * 4] = u;
        }
        __syncthreads();

#pragma unroll
        for (int ks = 0; ks < 4; ks++) {
            const int k0 = ks * 8;
            unsigned a[4][4], b[4][2];
#pragma unroll
            for (int mf = 0; mf < 4; mf++) {
                int m = warp_m * 64 + mf * 16 + g;
                a[mf][0] = As[k0 + tg][m];
                a[mf][1] = As[k0 + tg][m + 8];
                a[mf][2] = As[k0 + tg + 4][m];
                a[mf][3] = As[k0 + tg + 4][m + 8];
            }
#pragma unroll
            for (int nf = 0; nf < 4; nf++) {
                int n = warp_n * 32 + nf * 8 + g;
                b[nf][0] = Bs[k0 + tg][n];
                b[nf][1] = Bs[k0 + tg + 4][n];
            }
#pragma unroll
            for (int mf = 0; mf < 4; mf++)
#pragma unroll
                for (int nf = 0; nf < 4; nf++)
                    mma_tf32(acc[mf][nf], a[mf][0], a[mf][1], a[mf][2], a[mf][3],
                             b[nf][0], b[nf][1]);
        }
        __syncthreads();
    }

    // epilogue: add bias, float2 stores
#pragma unroll
    for (int mf = 0; mf < 4; mf++) {
        int row0 = m0 + warp_m * 64 + mf * 16 + g;
#pragma unroll
        for (int nf = 0; nf < 4; nf++) {
            int col = n0 + warp_n * 32 + nf * 8 + 2 * tg;
            float2 bv = *(const float2*)&bias[col];
            float2 o0, o1;
            o0.x = acc[mf][nf][0] + bv.x; o0.y = acc[mf][nf][1] + bv.y;
            o1.x = acc[mf][nf][2] + bv.x; o1.y = acc[mf][nf][3] + bv.y;
            *(float2*)&out[(size_t)row0 * D_MODEL + col] = o0;
            *(float2*)&out[(size_t)(row0 + 8) * D_MODEL + col] = o1;
        }
    }
}

// =====================================================================
// Kernel 2: banded scores (tf32 MMA) + softmax -> P
// Block = 64 queries x 320-key band, K=512 (Ktile 16).
// 8 warps as 2m x 4n, warp tile 32x80 -> 2 m-frags x 10 n-frags.
// =====================================================================
__global__ __launch_bounds__(256) void scores_mma()
{
    const int t0 = blockIdx.x * 64;
    const int b  = blockIdx.y;
    const float* Q = g_Q + (size_t)b * S_LEN * D_MODEL;
    const float* K = g_K + (size_t)b * S_LEN * D_MODEL;
    float* P = g_P + ((size_t)(b * NTILES + blockIdx.x)) * 64 * BAND;

    __shared__ unsigned As[16][72];     // Q^T tile (pre-scaled)
    __shared__ unsigned Bs[16][328];    // K band tile, transposed
    __shared__ float redm[64][4];
    __shared__ float reds[64][4];

    const int tid = threadIdx.x;
    const int warp = tid >> 5;
    const int lane = tid & 31;
    const int warp_m = warp >> 2;       // 0..1
    const int warp_n = warp & 3;        // 0..3
    const int g  = lane >> 2;
    const int tg = lane & 3;

    const float scale = 0.044194173824159216f;  // 1/sqrt(512)

    float acc[2][10][4];
#pragma unroll
    for (int mf = 0; mf < 2; mf++)
#pragma unroll
        for (int nf = 0; nf < 10; nf++)
#pragma unroll
            for (int c = 0; c < 4; c++) acc[mf][nf][c] = 0.f;

    for (int kb = 0; kb < D_MODEL; kb += 16) {
        // Q tile 64x16 = 256 float4, 1 per thread; scale + cvt + transpose
        {
            int row = tid >> 2;
            int k4  = tid & 3;
            float4 v = *(const float4*)&Q[(size_t)(t0 + row) * D_MODEL + kb + k4 * 4];
            As[k4 * 4 + 0][row] = f2tf(v.x * scale);
            As[k4 * 4 + 1][row] = f2tf(v.y * scale);
            As[k4 * 4 + 2][row] = f2tf(v.z * scale);
            As[k4 * 4 + 3][row] = f2tf(v.w * scale);
        }
        // K band tile 320x16 = 1280 float4, 5 per thread; cvt + transpose, OOB->0
#pragma unroll
        for (int i = 0; i < 5; i++) {
            int idx = i * 256 + tid;
            int row = idx >> 2;               // band col 0..319
            int k4  = idx & 3;
            int jg = t0 - HALF_W + row;
            float4 v = make_float4(0.f, 0.f, 0.f, 0.f);
            if (jg >= 0 && jg < S_LEN)
                v = *(const float4*)&K[(size_t)jg * D_MODEL + kb + k4 * 4];
            Bs[k4 * 4 + 0][row] = f2tf(v.x);
            Bs[k4 * 4 + 1][row] = f2tf(v.y);
            Bs[k4 * 4 + 2][row] = f2tf(v.z);
            Bs[k4 * 4 + 3][row] = f2tf(v.w);
        }
        __syncthreads();

#pragma unroll
        for (int ks = 0; ks < 2; ks++) {
            const int k0 = ks * 8;
            unsigned a[2][4], bfr[10][2];
#pragma unroll
            for (int mf = 0; mf < 2; mf++) {
                int m = warp_m * 32 + mf * 16 + g;
                a[mf][0] = As[k0 + tg][m];
                a[mf][1] = As[k0 + tg][m + 8];
                a[mf][2] = As[k0 + tg + 4][m];
                a[mf][3] = As[k0 + tg + 4][m + 8];
            }
#pragma unroll
            for (int nf = 0; nf < 10; nf++) {
                int n = warp_n * 80 + nf * 8 + g;
                bfr[nf][0] = Bs[k0 + tg][n];
                bfr[nf][1] = Bs[k0 + tg + 4][n];
            }
#pragma unroll
            for (int mf = 0; mf < 2; mf++)
#pragma unroll
                for (int nf = 0; nf < 10; nf++)
                    mma_tf32(acc[mf][nf], a[mf][0], a[mf][1], a[mf][2], a[mf][3],
                             bfr[nf][0], bfr[nf][1]);
        }
        __syncthreads();
    }

    // ---------- masking + row max ----------
    float rmax[2][2];
#pragma unroll
    for (int mf = 0; mf < 2; mf++)
#pragma unroll
        for (int h = 0; h < 2; h++) rmax[mf][h] = -INFINITY;

#pragma unroll
    for (int mf = 0; mf < 2; mf++) {
#pragma unroll
        for (int h = 0; h < 2; h++) {
            const int r = warp_m * 32 + mf * 16 + g + h * 8;
#pragma unroll
            for (int nf = 0; nf < 10; nf++) {
#pragma unroll
                for (int cc = 0; cc < 2; cc++) {
                    int c = warp_n * 80 + nf * 8 + 2 * tg + cc;
                    int jg = t0 - HALF_W + c;
                    bool valid = (c >= r) && (c <= r + 2 * HALF_W) && (jg >= 0) && (jg < S_LEN);
                    float v = valid ? acc[mf][nf][h * 2 + cc] : -INFINITY;
                    acc[mf][nf][h * 2 + cc] = v;
                    rmax[mf][h] = fmaxf(rmax[mf][h], v);
                }
            }
        }
    }
    // reduce within quarter (tg lanes)
#pragma unroll
    for (int mf = 0; mf < 2; mf++)
#pragma unroll
        for (int h = 0; h < 2; h++) {
            rmax[mf][h] = fmaxf(rmax[mf][h], __shfl_xor_sync(0xffffffffu, rmax[mf][h], 1));
            rmax[mf][h] = fmaxf(rmax[mf][h], __shfl_xor_sync(0xffffffffu, rmax[mf][h], 2));
        }
    if (tg == 0) {
#pragma unroll
        for (int mf = 0; mf < 2; mf++)
#pragma unroll
            for (int h = 0; h < 2; h++)
                redm[warp_m * 32 + mf * 16 + g + h * 8][warp_n] = rmax[mf][h];
    }
    __syncthreads();

    float gm[2][2];
#pragma unroll
    for (int mf = 0; mf < 2; mf++)
#pragma unroll
        for (int h = 0; h < 2; h++) {
            int r = warp_m * 32 + mf * 16 + g + h * 8;
            float m = redm[r][0];
            m = fmaxf(m, redm[r][1]);
            m = fmaxf(m, redm[r][2]);
            m = fmaxf(m, redm[r][3]);
            gm[mf][h] = m;
        }

    // ---------- exp + row sum ----------
    float rsum[2][2] = {{0.f, 0.f}, {0.f, 0.f}};
#pragma unroll
    for (int mf = 0; mf < 2; mf++)
#pragma unroll
        for (int h = 0; h < 2; h++)
#pragma unroll
            for (int nf = 0; nf < 10; nf++)
#pragma unroll
                for (int cc = 0; cc < 2; cc++) {
                    float e = __expf(acc[mf][nf][h * 2 + cc] - gm[mf][h]);
                    acc[mf][nf][h * 2 + cc] = e;
                    rsum[mf][h] += e;
                }
#pragma unroll
    for (int mf = 0; mf < 2; mf++)
#pragma unroll
        for (int h = 0; h < 2; h++) {
            rsum[mf][h] += __shfl_xor_sync(0xffffffffu, rsum[mf][h], 1);
            rsum[mf][h] += __shfl_xor_sync(0xffffffffu, rsum[mf][h], 2);
        }
    if (tg == 0) {
#pragma unroll
        for (int mf = 0; mf < 2; mf++)
#pragma unroll
            for (int h = 0; h < 2; h++)
                reds[warp_m * 32 + mf * 16 + g + h * 8][warp_n] = rsum[mf][h];
    }
    __syncthreads();

#pragma unroll
    for (int mf = 0; mf < 2; mf++) {
#pragma unroll
        for (int h = 0; h < 2; h++) {
            int r = warp_m * 32 + mf * 16 + g + h * 8;
            float s = reds[r][0] + reds[r][1] + reds[r][2] + reds[r][3];
            float inv = 1.0f / s;
#pragma unroll
            for (int nf = 0; nf < 10; nf++) {
                int c = warp_n * 80 + nf * 8 + 2 * tg;
                float2 o;
                o.x = acc[mf][nf][h * 2 + 0] * inv;
                o.y = acc[mf][nf][h * 2 + 1] * inv;
                *(float2*)&P[(size_t)r * BAND + c] = o;
            }
        }
    }
}

// =====================================================================
// Kernel 3: O = P @ V_band via tf32 MMA.
// Block tile 64x128 over N, K=320 (Ktile 32). 8 warps as 2m x 4n,
// warp tile 32x32 -> 2 m-frags x 4 n-frags.
// =====================================================================
__global__ __launch_bounds__(256) void out_mma(float* __restrict__ out)
{
    const int n0   = blockIdx.x * 128;
    const int tile = blockIdx.y;
    const int b    = blockIdx.z;
    const int t0   = tile * 64;

    const float* P = g_P + ((size_t)(b * NTILES + tile)) * 64 * BAND;
    const float* V = g_V + (size_t)b * S_LEN * D_MODEL;

    __shared__ unsigned As[32][72];     // P^T tile
    __shared__ unsigned Bs[32][136];    // V tile

    const int tid = threadIdx.x;
    const int warp = tid >> 5;
    const int lane = tid & 31;
    const int warp_m = warp >> 2;
    const int warp_n = warp & 3;
    const int g  = lane >> 2;
    const int tg = lane & 3;

    float acc[2][4][4];
#pragma unroll
    for (int mf = 0; mf < 2; mf++)
#pragma unroll
        for (int nf = 0; nf < 4; nf++)
#pragma unroll
            for (int c = 0; c < 4; c++) acc[mf][nf][c] = 0.f;

    for (int kb = 0; kb < BAND; kb += 32) {
        // P tile 64x32 = 512 float4, 2 per thread; transpose + cvt
#pragma unroll
        for (int i = 0; i < 2; i++) {
            int idx = i * 256 + tid;
            int row = idx >> 3;               // 0..63
            int k4  = idx & 7;                // 0..7
            float4 v = *(const float4*)&P[(size_t)row * BAND + kb + k4 * 4];
            As[k4 * 4 + 0][row] = f2tf(v.x);
            As[k4 * 4 + 1][row] = f2tf(v.y);
            As[k4 * 4 + 2][row] = f2tf(v.z);
            As[k4 * 4 + 3][row] = f2tf(v.w);
        }
        // V tile 32x128 = 1024 float4, 4 per thread; clamp rows (P==0 there)
#pragma unroll
        for (int i = 0; i < 4; i++) {
            int idx = i * 256 + tid;
            int kr = idx >> 5;                // 0..31
            int c4 = idx & 31;
            int jg = t0 - HALF_W + kb + kr;
            jg = max(0, min(S_LEN - 1, jg));
            float4 v = *(const float4*)&V[(size_t)jg * D_MODEL + n0 + c4 * 4];
            uint4 u = make_uint4(f2tf(v.x), f2tf(v.y), f2tf(v.z), f2tf(v.w));
            *(uint4*)&Bs[kr][c4 * 4] = u;
        }
        __syncthreads();

#pragma unroll
        for (int ks = 0; ks < 4; ks++) {
            const int k0 = ks * 8;
            unsigned a[2][4], bfr[4][2];
#pragma unroll
            for (int mf = 0; mf < 2; mf++) {
                int m = warp_m * 32 + mf * 16 + g;
                a[mf][0] = As[k0 + tg][m];
                a[mf][1] = As[k0 + tg][m + 8];
                a[mf][2] = As[k0 + tg + 4][m];
                a[mf][3] = As[k0 + tg + 4][m + 8];
            }
#pragma unroll
            for (int nf = 0; nf < 4; nf++) {
                int n = warp_n * 32 + nf * 8 + g;
                bfr[nf][0] = Bs[k0 + tg][n];
                bfr[nf][1] = Bs[k0 + tg + 4][n];
            }
#pragma unroll
            for (int mf = 0; mf < 2; mf++)
#pragma unroll
                for (int nf = 0; nf < 4; nf++)
                    mma_tf32(acc[mf][nf], a[mf][0], a[mf][1], a[mf][2], a[mf][3],
                             bfr[nf][0], bfr[nf][1]);
        }
        __syncthreads();
    }

#pragma unroll
    for (int mf = 0; mf < 2; mf++) {
        int row0 = t0 + warp_m * 32 + mf * 16 + g;
#pragma unroll
        for (int nf = 0; nf < 4; nf++) {
            int col = n0 + warp_n * 32 + nf * 8 + 2 * tg;
            float2 o0, o1;
            o0.x = acc[mf][nf][0]; o0.y = acc[mf][nf][1];
            o1.x = acc[mf][nf][2]; o1.y = acc[mf][nf][3];
            *(float2*)&out[((size_t)b * S_LEN + row0) * D_MODEL + col] = o0;
            *(float2*)&out[((size_t)b * S_LEN + row0 + 8) * D_MODEL + col] = o1;
        }
    }
}

// =====================================================================
extern "C" void kernel_launch(void* const* d_in, const int* in_sizes, int n_in,
                              void* d_out, int out_size)
{
    const float* x  = (const float*)d_in[0];
    const float* Wq = (const float*)d_in[1];
    const float* bq = (const float*)d_in[2];
    const float* Wk = (const float*)d_in[3];
    const float* bk = (const float*)d_in[4];
    const float* Wv = (const float*)d_in[5];
    const float* bv = (const float*)d_in[6];
    float* out = (float*)d_out;

    qkv_mma<<<dim3(D_MODEL / 128, (B_BATCH * S_LEN) / 128, 3), 256>>>(
        x, Wq, Wk, Wv, bq, bk, bv);

    scores_mma<<<dim3(NTILES, B_BATCH), 256>>>();

    out_mma<<<dim3(D_MODEL / 128, NTILES, B_BATCH), 256>>>(out);
}

// round 5
// speedup vs baseline: 3.2169x; 1.3108x over previous
#include <cuda_runtime.h>
#include <math.h>

#define B_BATCH 4
#define S_LEN   4096
#define D_MODEL 512
#define HALF_W  128
#define BAND    320
#define NTILES  (S_LEN / 64)

// ---------------- device scratch (no allocations allowed) ----------------
__device__ float g_Q[(size_t)B_BATCH * S_LEN * D_MODEL];
__device__ float g_K[(size_t)B_BATCH * S_LEN * D_MODEL];
__device__ float g_V[(size_t)B_BATCH * S_LEN * D_MODEL];
__device__ float g_P[(size_t)B_BATCH * NTILES * 64 * BAND];
__device__ float g_X[(size_t)B_BATCH * S_LEN * D_MODEL];     // tf32-rounded x
__device__ float g_W[3][(size_t)D_MODEL * D_MODEL];          // tf32-rounded Wq/Wk/Wv

// ---------------- helpers ----------------
__device__ __forceinline__ unsigned f2tf(float f) {
    unsigned r;
    asm("cvt.rna.tf32.f32 %0, %1;" : "=r"(r) : "f"(f));
    return r;
}

__device__ __forceinline__ void mma_tf32(float c[4],
                                         unsigned a0, unsigned a1, unsigned a2, unsigned a3,
                                         unsigned b0, unsigned b1) {
    asm volatile(
        "mma.sync.aligned.m16n8k8.row.col.f32.tf32.tf32.f32 "
        "{%0,%1,%2,%3}, {%4,%5,%6,%7}, {%8,%9}, {%0,%1,%2,%3};\n"
        : "+f"(c[0]), "+f"(c[1]), "+f"(c[2]), "+f"(c[3])
        : "r"(a0), "r"(a1), "r"(a2), "r"(a3), "r"(b0), "r"(b1));
}

__device__ __forceinline__ void cp16(void* dst_smem, const void* src, int szbytes) {
    unsigned d = (unsigned)__cvta_generic_to_shared(dst_smem);
    asm volatile("cp.async.cg.shared.global [%0], [%1], 16, %2;\n"
                 :: "r"(d), "l"(src), "r"(szbytes));
}
__device__ __forceinline__ void cp_commit() {
    asm volatile("cp.async.commit_group;\n");
}
template <int N> __device__ __forceinline__ void cp_wait() {
    asm volatile("cp.async.wait_group %0;\n" :: "n"(N));
}

// =====================================================================
// Kernel 0: tf32-round x and W into scratch (removes cvt from mainloops)
// =====================================================================
__global__ __launch_bounds__(256) void round_pre(
    const float* __restrict__ x,
    const float* __restrict__ Wq, const float* __restrict__ Wk, const float* __restrict__ Wv)
{
    const int z = blockIdx.y;   // 0: x, 1..3: W
    const float* src;
    float* dst;
    int n4;
    if (z == 0)      { src = x;  dst = g_X;    n4 = (B_BATCH * S_LEN * D_MODEL) / 4; }
    else if (z == 1) { src = Wq; dst = g_W[0]; n4 = (D_MODEL * D_MODEL) / 4; }
    else if (z == 2) { src = Wk; dst = g_W[1]; n4 = (D_MODEL * D_MODEL) / 4; }
    else             { src = Wv; dst = g_W[2]; n4 = (D_MODEL * D_MODEL) / 4; }

    int i = blockIdx.x * blockDim.x + threadIdx.x;
    int stride = gridDim.x * blockDim.x;
    for (; i < n4; i += stride) {
        float4 v = ((const float4*)src)[i];
        uint4 u = make_uint4(f2tf(v.x), f2tf(v.y), f2tf(v.z), f2tf(v.w));
        ((uint4*)dst)[i] = u;
    }
}

// =====================================================================
// Kernel 1: QKV projection, tf32 MMA, cp.async double-buffered.
// Block 128x128, BK=32, 256 thr (8 warps 2m x 4n), warp 64x32.
// Smem: A[2][128][36] (row-major m,k) + B[2][32][132] (k,n). 70656 B dynamic.
// =====================================================================
#define QKV_AS  (128 * 36)
#define QKV_BS  (32 * 132)
#define QKV_SMEM ((2 * QKV_AS + 2 * QKV_BS) * 4)

__global__ __launch_bounds__(256, 2) void qkv_mma(
    const float* __restrict__ bq, const float* __restrict__ bk, const float* __restrict__ bv)
{
    extern __shared__ unsigned smem[];
    unsigned* sA = smem;                 // [2][128][36]
    unsigned* sB = smem + 2 * QKV_AS;    // [2][32][132]

    const float* W;
    const float* bias;
    float* out;
    float oscale = 1.0f;
    if (blockIdx.z == 0)      { W = g_W[0]; bias = bq; out = g_Q; oscale = 0.044194173824159216f; }
    else if (blockIdx.z == 1) { W = g_W[1]; bias = bk; out = g_K; }
    else                      { W = g_W[2]; bias = bv; out = g_V; }

    const int m0 = blockIdx.y * 128;
    const int n0 = blockIdx.x * 128;
    const int tid = threadIdx.x;
    const int warp = tid >> 5;
    const int lane = tid & 31;
    const int warp_m = warp >> 2;
    const int warp_n = warp & 3;
    const int g  = lane >> 2;
    const int tg = lane & 3;

    // cp.async index precompute
    const int a_row = tid >> 3;          // +64 per i (4 chunks: idx = i*256+tid)
    const int a_k4  = (tid & 7) * 4;
    const int b_kr  = tid >> 5;          // +8 per i
    const int b_c4  = (tid & 31) * 4;

    float acc[4][4][4];
#pragma unroll
    for (int mf = 0; mf < 4; mf++)
#pragma unroll
        for (int nf = 0; nf < 4; nf++)
#pragma unroll
            for (int c = 0; c < 4; c++) acc[mf][nf][c] = 0.f;

    const int T = D_MODEL / 32;   // 16

    // ---- prologue: stage 0 ----
    {
        const int kb = 0;
#pragma unroll
        for (int i = 0; i < 4; i++) {
            int row = a_row + i * 32;
            cp16(&sA[(size_t)row * 36 + a_k4],
                 &g_X[(size_t)(m0 + row) * D_MODEL + kb + a_k4], 16);
        }
#pragma unroll
        for (int i = 0; i < 4; i++) {
            int kr = b_kr + i * 8;
            cp16(&sB[(size_t)kr * 132 + b_c4],
                 &W[(size_t)(kb + kr) * D_MODEL + n0 + b_c4], 16);
        }
        cp_commit();
    }

    for (int t = 0; t < T; t++) {
        if (t + 1 < T) {
            const int kb = (t + 1) * 32;
            unsigned* dA = sA + ((t + 1) & 1) * QKV_AS;
            unsigned* dB = sB + ((t + 1) & 1) * QKV_BS;
#pragma unroll
            for (int i = 0; i < 4; i++) {
                int row = a_row + i * 32;
                cp16(&dA[(size_t)row * 36 + a_k4],
                     &g_X[(size_t)(m0 + row) * D_MODEL + kb + a_k4], 16);
            }
#pragma unroll
            for (int i = 0; i < 4; i++) {
                int kr = b_kr + i * 8;
                cp16(&dB[(size_t)kr * 132 + b_c4],
                     &W[(size_t)(kb + kr) * D_MODEL + n0 + b_c4], 16);
            }
            cp_commit();
            cp_wait<1>();
        } else {
            cp_wait<0>();
        }
        __syncthreads();

        const unsigned* cA = sA + (t & 1) * QKV_AS;
        const unsigned* cB = sB + (t & 1) * QKV_BS;

#pragma unroll
        for (int ks = 0; ks < 4; ks++) {
            const int k0 = ks * 8;
            unsigned a[4][4], b[4][2];
#pragma unroll
            for (int mf = 0; mf < 4; mf++) {
                int m = warp_m * 64 + mf * 16 + g;
                a[mf][0] = cA[(size_t)m * 36 + k0 + tg];
                a[mf][1] = cA[(size_t)(m + 8) * 36 + k0 + tg];
                a[mf][2] = cA[(size_t)m * 36 + k0 + tg + 4];
                a[mf][3] = cA[(size_t)(m + 8) * 36 + k0 + tg + 4];
            }
#pragma unroll
            for (int nf = 0; nf < 4; nf++) {
                int n = warp_n * 32 + nf * 8 + g;
                b[nf][0] = cB[(size_t)(k0 + tg) * 132 + n];
                b[nf][1] = cB[(size_t)(k0 + tg + 4) * 132 + n];
            }
#pragma unroll
            for (int mf = 0; mf < 4; mf++)
#pragma unroll
                for (int nf = 0; nf < 4; nf++)
                    mma_tf32(acc[mf][nf], a[mf][0], a[mf][1], a[mf][2], a[mf][3],
                             b[nf][0], b[nf][1]);
        }
        __syncthreads();
    }

    // epilogue: bias, optional scale (Q), tf32 round, store
#pragma unroll
    for (int mf = 0; mf < 4; mf++) {
        int row0 = m0 + warp_m * 64 + mf * 16 + g;
#pragma unroll
        for (int nf = 0; nf < 4; nf++) {
            int col = n0 + warp_n * 32 + nf * 8 + 2 * tg;
            float2 bv = *(const float2*)&bias[col];
            float2 o0, o1;
            o0.x = __uint_as_float(f2tf((acc[mf][nf][0] + bv.x) * oscale));
            o0.y = __uint_as_float(f2tf((acc[mf][nf][1] + bv.y) * oscale));
            o1.x = __uint_as_float(f2tf((acc[mf][nf][2] + bv.x) * oscale));
            o1.y = __uint_as_float(f2tf((acc[mf][nf][3] + bv.y) * oscale));
            *(float2*)&out[(size_t)row0 * D_MODEL + col] = o0;
            *(float2*)&out[(size_t)(row0 + 8) * D_MODEL + col] = o1;
        }
    }
}

// =====================================================================
// Kernel 2: banded scores + softmax -> P (tf32, cp.async 2-stage)
// Block 64 x 320 band, BK=16. 8 warps 2m x 4n, warp 32x80.
// Smem: Q[2][64][20] + K[2][320][20] + red[64][8]. 63488 B dynamic.
// =====================================================================
#define SC_QS (64 * 20)
#define SC_KS (320 * 20)
#define SC_SMEM ((2 * SC_QS + 2 * SC_KS) * 4 + 64 * 8 * 4)

__global__ __launch_bounds__(256) void scores_mma()
{
    extern __shared__ unsigned smem[];
    unsigned* sQ = smem;                       // [2][64][20]
    unsigned* sK = smem + 2 * SC_QS;           // [2][320][20]
    float* redm = (float*)(smem + 2 * SC_QS + 2 * SC_KS);   // [64][4]
    float* reds = redm + 64 * 4;                            // [64][4]

    const int t0 = blockIdx.x * 64;
    const int b  = blockIdx.y;
    const float* Q = g_Q + (size_t)b * S_LEN * D_MODEL;
    const float* K = g_K + (size_t)b * S_LEN * D_MODEL;
    float* P = g_P + ((size_t)(b * NTILES + blockIdx.x)) * 64 * BAND;

    const int tid = threadIdx.x;
    const int warp = tid >> 5;
    const int lane = tid & 31;
    const int warp_m = warp >> 2;
    const int warp_n = warp & 3;
    const int g  = lane >> 2;
    const int tg = lane & 3;

    // cp.async indices: Q 64x16 -> 256 chunks (1/thr); K 320x16 -> 1280 (5/thr)
    const int q_row = tid >> 2;
    const int q_k4  = (tid & 3) * 4;

    float acc[2][10][4];
#pragma unroll
    for (int mf = 0; mf < 2; mf++)
#pragma unroll
        for (int nf = 0; nf < 10; nf++)
#pragma unroll
            for (int c = 0; c < 4; c++) acc[mf][nf][c] = 0.f;

    const int T = D_MODEL / 16;   // 32

    // prologue
    {
        const int kb = 0;
        cp16(&sQ[(size_t)q_row * 20 + q_k4],
             &Q[(size_t)(t0 + q_row) * D_MODEL + kb + q_k4], 16);
#pragma unroll
        for (int i = 0; i < 5; i++) {
            int idx = i * 256 + tid;
            int row = idx >> 2;
            int k4  = (idx & 3) * 4;
            int jg = t0 - HALF_W + row;
            int jc = max(0, min(S_LEN - 1, jg));
            int sz = (jg >= 0 && jg < S_LEN) ? 16 : 0;
            cp16(&sK[(size_t)row * 20 + k4],
                 &K[(size_t)jc * D_MODEL + kb + k4], sz);
        }
        cp_commit();
    }

    for (int t = 0; t < T; t++) {
        if (t + 1 < T) {
            const int kb = (t + 1) * 16;
            unsigned* dQ = sQ + ((t + 1) & 1) * SC_QS;
            unsigned* dK = sK + ((t + 1) & 1) * SC_KS;
            cp16(&dQ[(size_t)q_row * 20 + q_k4],
                 &Q[(size_t)(t0 + q_row) * D_MODEL + kb + q_k4], 16);
#pragma unroll
            for (int i = 0; i < 5; i++) {
                int idx = i * 256 + tid;
                int row = idx >> 2;
                int k4  = (idx & 3) * 4;
                int jg = t0 - HALF_W + row;
                int jc = max(0, min(S_LEN - 1, jg));
                int sz = (jg >= 0 && jg < S_LEN) ? 16 : 0;
                cp16(&dK[(size_t)row * 20 + k4],
                     &K[(size_t)jc * D_MODEL + kb + k4], sz);
            }
            cp_commit();
            cp_wait<1>();
        } else {
            cp_wait<0>();
        }
        __syncthreads();

        const unsigned* cQ = sQ + (t & 1) * SC_QS;
        const unsigned* cK = sK + (t & 1) * SC_KS;

#pragma unroll
        for (int ks = 0; ks < 2; ks++) {
            const int k0 = ks * 8;
            unsigned a[2][4], bfr[10][2];
#pragma unroll
            for (int mf = 0; mf < 2; mf++) {
                int m = warp_m * 32 + mf * 16 + g;
                a[mf][0] = cQ[(size_t)m * 20 + k0 + tg];
                a[mf][1] = cQ[(size_t)(m + 8) * 20 + k0 + tg];
                a[mf][2] = cQ[(size_t)m * 20 + k0 + tg + 4];
                a[mf][3] = cQ[(size_t)(m + 8) * 20 + k0 + tg + 4];
            }
#pragma unroll
            for (int nf = 0; nf < 10; nf++) {
                int n = warp_n * 80 + nf * 8 + g;
                bfr[nf][0] = cK[(size_t)n * 20 + k0 + tg];
                bfr[nf][1] = cK[(size_t)n * 20 + k0 + tg + 4];
            }
#pragma unroll
            for (int mf = 0; mf < 2; mf++)
#pragma unroll
                for (int nf = 0; nf < 10; nf++)
                    mma_tf32(acc[mf][nf], a[mf][0], a[mf][1], a[mf][2], a[mf][3],
                             bfr[nf][0], bfr[nf][1]);
        }
        __syncthreads();
    }

    // ---------- masking + row max ----------
    float rmax[2][2];
#pragma unroll
    for (int mf = 0; mf < 2; mf++)
#pragma unroll
        for (int h = 0; h < 2; h++) rmax[mf][h] = -INFINITY;

#pragma unroll
    for (int mf = 0; mf < 2; mf++)
#pragma unroll
        for (int h = 0; h < 2; h++) {
            const int r = warp_m * 32 + mf * 16 + g + h * 8;
#pragma unroll
            for (int nf = 0; nf < 10; nf++)
#pragma unroll
                for (int cc = 0; cc < 2; cc++) {
                    int c = warp_n * 80 + nf * 8 + 2 * tg + cc;
                    int jg = t0 - HALF_W + c;
                    bool valid = (c >= r) && (c <= r + 2 * HALF_W) && (jg >= 0) && (jg < S_LEN);
                    float v = valid ? acc[mf][nf][h * 2 + cc] : -INFINITY;
                    acc[mf][nf][h * 2 + cc] = v;
                    rmax[mf][h] = fmaxf(rmax[mf][h], v);
                }
        }
#pragma unroll
    for (int mf = 0; mf < 2; mf++)
#pragma unroll
        for (int h = 0; h < 2; h++) {
            rmax[mf][h] = fmaxf(rmax[mf][h], __shfl_xor_sync(0xffffffffu, rmax[mf][h], 1));
            rmax[mf][h] = fmaxf(rmax[mf][h], __shfl_xor_sync(0xffffffffu, rmax[mf][h], 2));
        }
    if (tg == 0)
#pragma unroll
        for (int mf = 0; mf < 2; mf++)
#pragma unroll
            for (int h = 0; h < 2; h++)
                redm[(warp_m * 32 + mf * 16 + g + h * 8) * 4 + warp_n] = rmax[mf][h];
    __syncthreads();

    float gm[2][2];
#pragma unroll
    for (int mf = 0; mf < 2; mf++)
#pragma unroll
        for (int h = 0; h < 2; h++) {
            int r = warp_m * 32 + mf * 16 + g + h * 8;
            float m = fmaxf(fmaxf(redm[r * 4 + 0], redm[r * 4 + 1]),
                            fmaxf(redm[r * 4 + 2], redm[r * 4 + 3]));
            gm[mf][h] = m;
        }

    // ---------- exp + row sum ----------
    float rsum[2][2] = {{0.f, 0.f}, {0.f, 0.f}};
#pragma unroll
    for (int mf = 0; mf < 2; mf++)
#pragma unroll
        for (int h = 0; h < 2; h++)
#pragma unroll
            for (int nf = 0; nf < 10; nf++)
#pragma unroll
                for (int cc = 0; cc < 2; cc++) {
                    float e = __expf(acc[mf][nf][h * 2 + cc] - gm[mf][h]);
                    acc[mf][nf][h * 2 + cc] = e;
                    rsum[mf][h] += e;
                }
#pragma unroll
    for (int mf = 0; mf < 2; mf++)
#pragma unroll
        for (int h = 0; h < 2; h++) {
            rsum[mf][h] += __shfl_xor_sync(0xffffffffu, rsum[mf][h], 1);
            rsum[mf][h] += __shfl_xor_sync(0xffffffffu, rsum[mf][h], 2);
        }
    if (tg == 0)
#pragma unroll
        for (int mf = 0; mf < 2; mf++)
#pragma unroll
            for (int h = 0; h < 2; h++)
                reds[(warp_m * 32 + mf * 16 + g + h * 8) * 4 + warp_n] = rsum[mf][h];
    __syncthreads();

#pragma unroll
    for (int mf = 0; mf < 2; mf++)
#pragma unroll
        for (int h = 0; h < 2; h++) {
            int r = warp_m * 32 + mf * 16 + g + h * 8;
            float s = reds[r * 4 + 0] + reds[r * 4 + 1] + reds[r * 4 + 2] + reds[r * 4 + 3];
            float inv = 1.0f / s;
#pragma unroll
            for (int nf = 0; nf < 10; nf++) {
                int c = warp_n * 80 + nf * 8 + 2 * tg;
                float2 o;
                o.x = __uint_as_float(f2tf(acc[mf][nf][h * 2 + 0] * inv));
                o.y = __uint_as_float(f2tf(acc[mf][nf][h * 2 + 1] * inv));
                *(float2*)&P[(size_t)r * BAND + c] = o;
            }
        }
}

// =====================================================================
// Kernel 3: O = P @ V_band (tf32, cp.async 2-stage)
// Block 64x128, K=320, BK=32. 8 warps 2m x 4n, warp 32x32.
// Smem: P[2][64][36] + V[2][32][132]. 52224 B dynamic.
// =====================================================================
#define OU_PS (64 * 36)
#define OU_VS (32 * 132)
#define OU_SMEM ((2 * OU_PS + 2 * OU_VS) * 4)

__global__ __launch_bounds__(256, 2) void out_mma(float* __restrict__ out)
{
    extern __shared__ unsigned smem[];
    unsigned* sP = smem;                 // [2][64][36]
    unsigned* sV = smem + 2 * OU_PS;     // [2][32][132]

    const int n0   = blockIdx.x * 128;
    const int tile = blockIdx.y;
    const int b    = blockIdx.z;
    const int t0   = tile * 64;

    const float* P = g_P + ((size_t)(b * NTILES + tile)) * 64 * BAND;
    const float* V = g_V + (size_t)b * S_LEN * D_MODEL;

    const int tid = threadIdx.x;
    const int warp = tid >> 5;
    const int lane = tid & 31;
    const int warp_m = warp >> 2;
    const int warp_n = warp & 3;
    const int g  = lane >> 2;
    const int tg = lane & 3;

    // cp.async indices: P 64x32 -> 512 chunks (2/thr); V 32x128 -> 1024 (4/thr)
    const int p_row = tid >> 3;          // +32 per i
    const int p_k4  = (tid & 7) * 4;
    const int v_kr  = tid >> 5;          // +8 per i
    const int v_c4  = (tid & 31) * 4;

    float acc[2][4][4];
#pragma unroll
    for (int mf = 0; mf < 2; mf++)
#pragma unroll
        for (int nf = 0; nf < 4; nf++)
#pragma unroll
            for (int c = 0; c < 4; c++) acc[mf][nf][c] = 0.f;

    const int T = BAND / 32;   // 10

    // prologue
    {
        const int kb = 0;
#pragma unroll
        for (int i = 0; i < 2; i++) {
            int row = p_row + i * 32;
            cp16(&sP[(size_t)row * 36 + p_k4], &P[(size_t)row * BAND + kb + p_k4], 16);
        }
#pragma unroll
        for (int i = 0; i < 4; i++) {
            int kr = v_kr + i * 8;
            int jg = t0 - HALF_W + kb + kr;
            jg = max(0, min(S_LEN - 1, jg));
            cp16(&sV[(size_t)kr * 132 + v_c4], &V[(size_t)jg * D_MODEL + n0 + v_c4], 16);
        }
        cp_commit();
    }

    for (int t = 0; t < T; t++) {
        if (t + 1 < T) {
            const int kb = (t + 1) * 32;
            unsigned* dP = sP + ((t + 1) & 1) * OU_PS;
            unsigned* dV = sV + ((t + 1) & 1) * OU_VS;
#pragma unroll
            for (int i = 0; i < 2; i++) {
                int row = p_row + i * 32;
                cp16(&dP[(size_t)row * 36 + p_k4], &P[(size_t)row * BAND + kb + p_k4], 16);
            }
#pragma unroll
            for (int i = 0; i < 4; i++) {
                int kr = v_kr + i * 8;
                int jg = t0 - HALF_W + kb + kr;
                jg = max(0, min(S_LEN - 1, jg));
                cp16(&dV[(size_t)kr * 132 + v_c4], &V[(size_t)jg * D_MODEL + n0 + v_c4], 16);
            }
            cp_commit();
            cp_wait<1>();
        } else {
            cp_wait<0>();
        }
        __syncthreads();

        const unsigned* cP = sP + (t & 1) * OU_PS;
        const unsigned* cV = sV + (t & 1) * OU_VS;

#pragma unroll
        for (int ks = 0; ks < 4; ks++) {
            const int k0 = ks * 8;
            unsigned a[2][4], bfr[4][2];
#pragma unroll
            for (int mf = 0; mf < 2; mf++) {
                int m = warp_m * 32 + mf * 16 + g;
                a[mf][0] = cP[(size_t)m * 36 + k0 + tg];
                a[mf][1] = cP[(size_t)(m + 8) * 36 + k0 + tg];
                a[mf][2] = cP[(size_t)m * 36 + k0 + tg + 4];
                a[mf][3] = cP[(size_t)(m + 8) * 36 + k0 + tg + 4];
            }
#pragma unroll
            for (int nf = 0; nf < 4; nf++) {
                int n = warp_n * 32 + nf * 8 + g;
                bfr[nf][0] = cV[(size_t)(k0 + tg) * 132 + n];
                bfr[nf][1] = cV[(size_t)(k0 + tg + 4) * 132 + n];
            }
#pragma unroll
            for (int mf = 0; mf < 2; mf++)
#pragma unroll
                for (int nf = 0; nf < 4; nf++)
                    mma_tf32(acc[mf][nf], a[mf][0], a[mf][1], a[mf][2], a[mf][3],
                             bfr[nf][0], bfr[nf][1]);
        }
        __syncthreads();
    }

#pragma unroll
    for (int mf = 0; mf < 2; mf++) {
        int row0 = t0 + warp_m * 32 + mf * 16 + g;
#pragma unroll
        for (int nf = 0; nf < 4; nf++) {
            int col = n0 + warp_n * 32 + nf * 8 + 2 * tg;
            float2 o0, o1;
            o0.x = acc[mf][nf][0]; o0.y = acc[mf][nf][1];
            o1.x = acc[mf][nf][2]; o1.y = acc[mf][nf][3];
            *(float2*)&out[((size_t)b * S_LEN + row0) * D_MODEL + col] = o0;
            *(float2*)&out[((size_t)b * S_LEN + row0 + 8) * D_MODEL + col] = o1;
        }
    }
}

// =====================================================================
extern "C" void kernel_launch(void* const* d_in, const int* in_sizes, int n_in,
                              void* d_out, int out_size)
{
    const float* x  = (const float*)d_in[0];
    const float* Wq = (const float*)d_in[1];
    const float* bq = (const float*)d_in[2];
    const float* Wk = (const float*)d_in[3];
    const float* bk = (const float*)d_in[4];
    const float* Wv = (const float*)d_in[5];
    const float* bv = (const float*)d_in[6];
    float* out = (float*)d_out;

    // idempotent attribute sets (immediate, not captured as graph nodes)
    cudaFuncSetAttribute(qkv_mma, cudaFuncAttributeMaxDynamicSharedMemorySize, QKV_SMEM);
    cudaFuncSetAttribute(scores_mma, cudaFuncAttributeMaxDynamicSharedMemorySize, SC_SMEM);
    cudaFuncSetAttribute(out_mma, cudaFuncAttributeMaxDynamicSharedMemorySize, OU_SMEM);

    round_pre<<<dim3(2048, 4), 256>>>(x, Wq, Wk, Wv);

    qkv_mma<<<dim3(D_MODEL / 128, (B_BATCH * S_LEN) / 128, 3), 256, QKV_SMEM>>>(bq, bk, bv);

    scores_mma<<<dim3(NTILES, B_BATCH), 256, SC_SMEM>>>();

    out_mma<<<dim3(D_MODEL / 128, NTILES, B_BATCH), 256, OU_SMEM>>>(out);
}

// round 7
// speedup vs baseline: 3.6599x; 1.1377x over previous
#include <cuda_runtime.h>
#include <math.h>
#include <stdint.h>

#define B_BATCH 4
#define S_LEN   4096
#define D_MODEL 512
#define HALF_W  128
#define BAND    320
#define NTILES  (S_LEN / 64)

#define M_ALL   (B_BATCH * S_LEN)          // 16384 rows
#define MT_ALL  (M_ALL / 16)               // 1024 m-tiles
#define KT_ALL  (D_MODEL / 8)              // 64 k-tiles
#define NT_ALL  (D_MODEL / 8)              // 64 n-tiles
#define WP_SZ   ((size_t)NT_ALL * KT_ALL * 32 * 2)   // per-matrix packed W floats

// ---------------- device scratch (no allocations allowed) ----------------
__device__ float g_Q[(size_t)B_BATCH * S_LEN * D_MODEL];
__device__ float g_K[(size_t)B_BATCH * S_LEN * D_MODEL];
__device__ float g_V[(size_t)B_BATCH * S_LEN * D_MODEL];
__device__ float g_P[(size_t)B_BATCH * NTILES * 64 * BAND];
__device__ float g_Xp[(size_t)MT_ALL * KT_ALL * 32 * 4];   // a-frag-packed x (tf32)
__device__ float g_Wp[3][WP_SZ];                           // b-frag-packed W (tf32)

// ---------------- helpers ----------------
__device__ __forceinline__ unsigned f2tf(float f) {
    unsigned r;
    asm("cvt.rna.tf32.f32 %0, %1;" : "=r"(r) : "f"(f));
    return r;
}

__device__ __forceinline__ void mma_tf32(float c[4],
                                         unsigned a0, unsigned a1, unsigned a2, unsigned a3,
                                         unsigned b0, unsigned b1) {
    asm volatile(
        "mma.sync.aligned.m16n8k8.row.col.f32.tf32.tf32.f32 "
        "{%0,%1,%2,%3}, {%4,%5,%6,%7}, {%8,%9}, {%0,%1,%2,%3};\n"
        : "+f"(c[0]), "+f"(c[1]), "+f"(c[2]), "+f"(c[3])
        : "r"(a0), "r"(a1), "r"(a2), "r"(a3), "r"(b0), "r"(b1));
}

__device__ __forceinline__ void cp16(void* dst_smem, const void* src, int szbytes) {
    unsigned d = (unsigned)__cvta_generic_to_shared(dst_smem);
    asm volatile("cp.async.cg.shared.global [%0], [%1], 16, %2;\n"
                 :: "r"(d), "l"(src), "r"(szbytes));
}
__device__ __forceinline__ void cp_commit() {
    asm volatile("cp.async.commit_group;\n");
}
template <int N> __device__ __forceinline__ void cp_wait() {
    asm volatile("cp.async.wait_group %0;\n" :: "n"(N));
}

// =====================================================================
// Kernel 0a: pack x into a-fragment order (tf32-rounded).
// g_Xp[((mt*64 + kt)*32 + lane)*4 + r]:
//   r0=(g,tg) r1=(g+8,tg) r2=(g,tg+4) r3=(g+8,tg+4), lane = g*4+tg
// =====================================================================
__global__ __launch_bounds__(256) void pack_x(const float* __restrict__ x)
{
    int c = blockIdx.x * blockDim.x + threadIdx.x;      // chunk id, 1 chunk = 16B
    const int total = MT_ALL * KT_ALL * 32;
    if (c >= total) return;
    int lane = c & 31;
    int kt = (c >> 5) & (KT_ALL - 1);
    int mt = c >> 11;                                   // c / (64*32)
    int g = lane >> 2, tg = lane & 3;
    const float* p = x + (size_t)(mt * 16 + g) * D_MODEL + kt * 8 + tg;
    uint4 u;
    u.x = f2tf(p[0]);
    u.y = f2tf(p[8 * D_MODEL]);
    u.z = f2tf(p[4]);
    u.w = f2tf(p[8 * D_MODEL + 4]);
    *(uint4*)&g_Xp[(size_t)c * 4] = u;
}

// =====================================================================
// Kernel 0b: pack W into b-fragment order (tf32-rounded).
// g_Wp[z][((nt*64 + kt)*32 + lane)*2 + r]: r0=W[kt*8+tg][nt*8+g], r1=+4 row
// =====================================================================
__global__ __launch_bounds__(256) void pack_w(
    const float* __restrict__ Wq, const float* __restrict__ Wk, const float* __restrict__ Wv)
{
    const float* src = (blockIdx.y == 0) ? Wq : (blockIdx.y == 1) ? Wk : Wv;
    float* dst = g_Wp[blockIdx.y];
    int c = blockIdx.x * blockDim.x + threadIdx.x;      // 1 chunk = 8B (2 floats)
    const int total = NT_ALL * KT_ALL * 32;
    if (c >= total) return;
    int lane = c & 31;
    int kt = (c >> 5) & (KT_ALL - 1);
    int nt = c >> 11;
    int g = lane >> 2, tg = lane & 3;
    const float* p = src + (size_t)(kt * 8 + tg) * D_MODEL + nt * 8 + g;
    float2 o;
    o.x = __uint_as_float(f2tf(p[0]));
    o.y = __uint_as_float(f2tf(p[4 * D_MODEL]));
    *(float2*)&dst[(size_t)c * 2] = o;
}

// =====================================================================
// Kernel 1: QKV projection, tf32 MMA, fragment-packed operands.
// Block 128x128, BK=32, 256 thr (8 warps 2m x 4n), warp 64x32.
// Smem per stage: A 4096 floats + B 4096 floats (no padding needed).
// Frag loads: LDS.128 (a) / LDS.64 (b), conflict-free by construction.
// =====================================================================
#define QKV_AS  4096
#define QKV_BS  4096
#define QKV_SMEM ((2 * QKV_AS + 2 * QKV_BS) * 4)   // 65536 B

__global__ __launch_bounds__(256, 2) void qkv_mma(
    const float* __restrict__ bq, const float* __restrict__ bk, const float* __restrict__ bv)
{
    extern __shared__ float smem[];
    float* sA = smem;                  // [2][8 mt][4 kt][32 lane][4]
    float* sB = smem + 2 * QKV_AS;     // [2][16 nt][4 kt][32 lane][2]

    const int z = blockIdx.z;
    const float* Wp   = g_Wp[z];
    const float* bias = (z == 0) ? bq : (z == 1) ? bk : bv;
    float* out        = (z == 0) ? g_Q : (z == 1) ? g_K : g_V;
    const float oscale = (z == 0) ? 0.044194173824159216f : 1.0f;

    const int m0 = blockIdx.y * 128;
    const int n0 = blockIdx.x * 128;
    const int mt0 = m0 >> 4;
    const int nt0 = n0 >> 3;
    const int tid = threadIdx.x;
    const int warp = tid >> 5;
    const int lane = tid & 31;
    const int warp_m = warp >> 2;       // 0..1
    const int warp_n = warp & 3;        // 0..3
    const int g  = lane >> 2;
    const int tg = lane & 3;

    float acc[4][4][4];
#pragma unroll
    for (int mf = 0; mf < 4; mf++)
#pragma unroll
        for (int nf = 0; nf < 4; nf++)
#pragma unroll
            for (int c = 0; c < 4; c++) acc[mf][nf][c] = 0.f;

    const int T = D_MODEL / 32;   // 16 stages

    // stage loader: A 1024 chunks (4/thr), B 1024 chunks (4/thr)
    auto load_stage = [&](int s) {
        float* dA = sA + (s & 1) * QKV_AS;
        float* dB = sB + (s & 1) * QKV_BS;
        const int ktb = s * 4;          // first k-tile of this stage
#pragma unroll
        for (int i = 0; i < 4; i++) {
            int c = i * 256 + tid;
            int mt = c >> 7;
            int kt = (c >> 5) & 3;
            int ln = c & 31;
            cp16(&dA[((mt * 4 + kt) * 32 + ln) * 4],
                 &g_Xp[(((size_t)(mt0 + mt) * KT_ALL + ktb + kt) * 32 + ln) * 4], 16);
        }
#pragma unroll
        for (int i = 0; i < 4; i++) {
            int c = i * 256 + tid;
            int nt = c >> 6;
            int kt = (c >> 4) & 3;
            int pr = c & 15;            // 2 lanes per 16B chunk
            cp16(&dB[(nt * 4 + kt) * 64 + pr * 4],
                 &Wp[(((size_t)(nt0 + nt) * KT_ALL + ktb + kt) * 32) * 2 + pr * 4], 16);
        }
        cp_commit();
    };

    load_stage(0);

    for (int t = 0; t < T; t++) {
        if (t + 1 < T) {
            load_stage(t + 1);
            cp_wait<1>();
        } else {
            cp_wait<0>();
        }
        __syncthreads();

        const float* cA = sA + (t & 1) * QKV_AS;
        const float* cB = sB + (t & 1) * QKV_BS;

#pragma unroll
        for (int ks = 0; ks < 4; ks++) {
            uint4 a[4];
            uint2 b[4];
#pragma unroll
            for (int mf = 0; mf < 4; mf++)
                a[mf] = *(const uint4*)&cA[(((warp_m * 4 + mf) * 4 + ks) * 32 + lane) * 4];
#pragma unroll
            for (int nf = 0; nf < 4; nf++)
                b[nf] = *(const uint2*)&cB[((warp_n * 4 + nf) * 4 + ks) * 64 + lane * 2];
#pragma unroll
            for (int mf = 0; mf < 4; mf++)
#pragma unroll
                for (int nf = 0; nf < 4; nf++)
                    mma_tf32(acc[mf][nf], a[mf].x, a[mf].y, a[mf].z, a[mf].w,
                             b[nf].x, b[nf].y);
        }
        __syncthreads();
    }

    // epilogue: bias, optional scale (Q), tf32 round, row-major store
#pragma unroll
    for (int mf = 0; mf < 4; mf++) {
        int row0 = m0 + warp_m * 64 + mf * 16 + g;
#pragma unroll
        for (int nf = 0; nf < 4; nf++) {
            int col = n0 + warp_n * 32 + nf * 8 + 2 * tg;
            float2 bv = *(const float2*)&bias[col];
            float2 o0, o1;
            o0.x = __uint_as_float(f2tf((acc[mf][nf][0] + bv.x) * oscale));
            o0.y = __uint_as_float(f2tf((acc[mf][nf][1] + bv.y) * oscale));
            o1.x = __uint_as_float(f2tf((acc[mf][nf][2] + bv.x) * oscale));
            o1.y = __uint_as_float(f2tf((acc[mf][nf][3] + bv.y) * oscale));
            *(float2*)&out[(size_t)row0 * D_MODEL + col] = o0;
            *(float2*)&out[(size_t)(row0 + 8) * D_MODEL + col] = o1;
        }
    }
}

// =====================================================================
// Kernel 2: banded scores + softmax -> P (tf32 mma.sync, cp.async 2-stage)
// (unchanged from passing R5 version)
// =====================================================================
#define SC_QS (64 * 20)
#define SC_KS (320 * 20)
#define SC_SMEM ((2 * SC_QS + 2 * SC_KS) * 4 + 64 * 8 * 4)

__global__ __launch_bounds__(256) void scores_mma()
{
    extern __shared__ unsigned smemu[];
    unsigned* sQ = smemu;
    unsigned* sK = smemu + 2 * SC_QS;
    float* redm = (float*)(smemu + 2 * SC_QS + 2 * SC_KS);
    float* reds = redm + 64 * 4;

    const int t0 = blockIdx.x * 64;
    const int b  = blockIdx.y;
    const float* Q = g_Q + (size_t)b * S_LEN * D_MODEL;
    const float* K = g_K + (size_t)b * S_LEN * D_MODEL;
    float* P = g_P + ((size_t)(b * NTILES + blockIdx.x)) * 64 * BAND;

    const int tid = threadIdx.x;
    const int warp = tid >> 5;
    const int lane = tid & 31;
    const int warp_m = warp >> 2;
    const int warp_n = warp & 3;
    const int g  = lane >> 2;
    const int tg = lane & 3;

    const int q_row = tid >> 2;
    const int q_k4  = (tid & 3) * 4;

    float acc[2][10][4];
#pragma unroll
    for (int mf = 0; mf < 2; mf++)
#pragma unroll
        for (int nf = 0; nf < 10; nf++)
#pragma unroll
            for (int c = 0; c < 4; c++) acc[mf][nf][c] = 0.f;

    const int T = D_MODEL / 16;

    {
        const int kb = 0;
        cp16(&sQ[(size_t)q_row * 20 + q_k4],
             &Q[(size_t)(t0 + q_row) * D_MODEL + kb + q_k4], 16);
#pragma unroll
        for (int i = 0; i < 5; i++) {
            int idx = i * 256 + tid;
            int row = idx >> 2;
            int k4  = (idx & 3) * 4;
            int jg = t0 - HALF_W + row;
            int jc = max(0, min(S_LEN - 1, jg));
            int sz = (jg >= 0 && jg < S_LEN) ? 16 : 0;
            cp16(&sK[(size_t)row * 20 + k4],
                 &K[(size_t)jc * D_MODEL + kb + k4], sz);
        }
        cp_commit();
    }

    for (int t = 0; t < T; t++) {
        if (t + 1 < T) {
            const int kb = (t + 1) * 16;
            unsigned* dQ = sQ + ((t + 1) & 1) * SC_QS;
            unsigned* dK = sK + ((t + 1) & 1) * SC_KS;
            cp16(&dQ[(size_t)q_row * 20 + q_k4],
                 &Q[(size_t)(t0 + q_row) * D_MODEL + kb + q_k4], 16);
#pragma unroll
            for (int i = 0; i < 5; i++) {
                int idx = i * 256 + tid;
                int row = idx >> 2;
                int k4  = (idx & 3) * 4;
                int jg = t0 - HALF_W + row;
                int jc = max(0, min(S_LEN - 1, jg));
                int sz = (jg >= 0 && jg < S_LEN) ? 16 : 0;
                cp16(&dK[(size_t)row * 20 + k4],
                     &K[(size_t)jc * D_MODEL + kb + k4], sz);
            }
            cp_commit();
            cp_wait<1>();
        } else {
            cp_wait<0>();
        }
        __syncthreads();

        const unsigned* cQ = sQ + (t & 1) * SC_QS;
        const unsigned* cK = sK + (t & 1) * SC_KS;

#pragma unroll
        for (int ks = 0; ks < 2; ks++) {
            const int k0 = ks * 8;
            unsigned a[2][4], bfr[10][2];
#pragma unroll
            for (int mf = 0; mf < 2; mf++) {
                int m = warp_m * 32 + mf * 16 + g;
                a[mf][0] = cQ[(size_t)m * 20 + k0 + tg];
                a[mf][1] = cQ[(size_t)(m + 8) * 20 + k0 + tg];
                a[mf][2] = cQ[(size_t)m * 20 + k0 + tg + 4];
                a[mf][3] = cQ[(size_t)(m + 8) * 20 + k0 + tg + 4];
            }
#pragma unroll
            for (int nf = 0; nf < 10; nf++) {
                int n = warp_n * 80 + nf * 8 + g;
                bfr[nf][0] = cK[(size_t)n * 20 + k0 + tg];
                bfr[nf][1] = cK[(size_t)n * 20 + k0 + tg + 4];
            }
#pragma unroll
            for (int mf = 0; mf < 2; mf++)
#pragma unroll
                for (int nf = 0; nf < 10; nf++)
                    mma_tf32(acc[mf][nf], a[mf][0], a[mf][1], a[mf][2], a[mf][3],
                             bfr[nf][0], bfr[nf][1]);
        }
        __syncthreads();
    }

    float rmax[2][2];
#pragma unroll
    for (int mf = 0; mf < 2; mf++)
#pragma unroll
        for (int h = 0; h < 2; h++) rmax[mf][h] = -INFINITY;

#pragma unroll
    for (int mf = 0; mf < 2; mf++)
#pragma unroll
        for (int h = 0; h < 2; h++) {
            const int r = warp_m * 32 + mf * 16 + g + h * 8;
#pragma unroll
            for (int nf = 0; nf < 10; nf++)
#pragma unroll
                for (int cc = 0; cc < 2; cc++) {
                    int c = warp_n * 80 + nf * 8 + 2 * tg + cc;
                    int jg = t0 - HALF_W + c;
                    bool valid = (c >= r) && (c <= r + 2 * HALF_W) && (jg >= 0) && (jg < S_LEN);
                    float v = valid ? acc[mf][nf][h * 2 + cc] : -INFINITY;
                    acc[mf][nf][h * 2 + cc] = v;
                    rmax[mf][h] = fmaxf(rmax[mf][h], v);
                }
        }
#pragma unroll
    for (int mf = 0; mf < 2; mf++)
#pragma unroll
        for (int h = 0; h < 2; h++) {
            rmax[mf][h] = fmaxf(rmax[mf][h], __shfl_xor_sync(0xffffffffu, rmax[mf][h], 1));
            rmax[mf][h] = fmaxf(rmax[mf][h], __shfl_xor_sync(0xffffffffu, rmax[mf][h], 2));
        }
    if (tg == 0)
#pragma unroll
        for (int mf = 0; mf < 2; mf++)
#pragma unroll
            for (int h = 0; h < 2; h++)
                redm[(warp_m * 32 + mf * 16 + g + h * 8) * 4 + warp_n] = rmax[mf][h];
    __syncthreads();

    float gm[2][2];
#pragma unroll
    for (int mf = 0; mf < 2; mf++)
#pragma unroll
        for (int h = 0; h < 2; h++) {
            int r = warp_m * 32 + mf * 16 + g + h * 8;
            gm[mf][h] = fmaxf(fmaxf(redm[r * 4 + 0], redm[r * 4 + 1]),
                              fmaxf(redm[r * 4 + 2], redm[r * 4 + 3]));
        }

    float rsum[2][2] = {{0.f, 0.f}, {0.f, 0.f}};
#pragma unroll
    for (int mf = 0; mf < 2; mf++)
#pragma unroll
        for (int h = 0; h < 2; h++)
#pragma unroll
            for (int nf = 0; nf < 10; nf++)
#pragma unroll
                for (int cc = 0; cc < 2; cc++) {
                    float e = __expf(acc[mf][nf][h * 2 + cc] - gm[mf][h]);
                    acc[mf][nf][h * 2 + cc] = e;
                    rsum[mf][h] += e;
                }
#pragma unroll
    for (int mf = 0; mf < 2; mf++)
#pragma unroll
        for (int h = 0; h < 2; h++) {
            rsum[mf][h] += __shfl_xor_sync(0xffffffffu, rsum[mf][h], 1);
            rsum[mf][h] += __shfl_xor_sync(0xffffffffu, rsum[mf][h], 2);
        }
    if (tg == 0)
#pragma unroll
        for (int mf = 0; mf < 2; mf++)
#pragma unroll
            for (int h = 0; h < 2; h++)
                reds[(warp_m * 32 + mf * 16 + g + h * 8) * 4 + warp_n] = rsum[mf][h];
    __syncthreads();

#pragma unroll
    for (int mf = 0; mf < 2; mf++)
#pragma unroll
        for (int h = 0; h < 2; h++) {
            int r = warp_m * 32 + mf * 16 + g + h * 8;
            float s = reds[r * 4 + 0] + reds[r * 4 + 1] + reds[r * 4 + 2] + reds[r * 4 + 3];
            float inv = 1.0f / s;
#pragma unroll
            for (int nf = 0; nf < 10; nf++) {
                int c = warp_n * 80 + nf * 8 + 2 * tg;
                float2 o;
                o.x = __uint_as_float(f2tf(acc[mf][nf][h * 2 + 0] * inv));
                o.y = __uint_as_float(f2tf(acc[mf][nf][h * 2 + 1] * inv));
                *(float2*)&P[(size_t)r * BAND + c] = o;
            }
        }
}

// =====================================================================
// Kernel 3: O = P @ V_band (tf32 mma.sync, cp.async 2-stage)
// (unchanged from passing R5 version)
// =====================================================================
#define OU_PS (64 * 36)
#define OU_VS (32 * 132)
#define OU_SMEM ((2 * OU_PS + 2 * OU_VS) * 4)

__global__ __launch_bounds__(256, 2) void out_mma(float* __restrict__ out)
{
    extern __shared__ unsigned smemu[];
    unsigned* sP = smemu;
    unsigned* sV = smemu + 2 * OU_PS;

    const int n0   = blockIdx.x * 128;
    const int tile = blockIdx.y;
    const int b    = blockIdx.z;
    const int t0   = tile * 64;

    const float* P = g_P + ((size_t)(b * NTILES + tile)) * 64 * BAND;
    const float* V = g_V + (size_t)b * S_LEN * D_MODEL;

    const int tid = threadIdx.x;
    const int warp = tid >> 5;
    const int lane = tid & 31;
    const int warp_m = warp >> 2;
    const int warp_n = warp & 3;
    const int g  = lane >> 2;
    const int tg = lane & 3;

    const int p_row = tid >> 3;
    const int p_k4  = (tid & 7) * 4;
    const int v_kr  = tid >> 5;
    const int v_c4  = (tid & 31) * 4;

    float acc[2][4][4];
#pragma unroll
    for (int mf = 0; mf < 2; mf++)
#pragma unroll
        for (int nf = 0; nf < 4; nf++)
#pragma unroll
            for (int c = 0; c < 4; c++) acc[mf][nf][c] = 0.f;

    const int T = BAND / 32;

    {
        const int kb = 0;
#pragma unroll
        for (int i = 0; i < 2; i++) {
            int row = p_row + i * 32;
            cp16(&sP[(size_t)row * 36 + p_k4], &P[(size_t)row * BAND + kb + p_k4], 16);
        }
#pragma unroll
        for (int i = 0; i < 4; i++) {
            int kr = v_kr + i * 8;
            int jg = t0 - HALF_W + kb + kr;
            jg = max(0, min(S_LEN - 1, jg));
            cp16(&sV[(size_t)kr * 132 + v_c4], &V[(size_t)jg * D_MODEL + n0 + v_c4], 16);
        }
        cp_commit();
    }

    for (int t = 0; t < T; t++) {
        if (t + 1 < T) {
            const int kb = (t + 1) * 32;
            unsigned* dP = sP + ((t + 1) & 1) * OU_PS;
            unsigned* dV = sV + ((t + 1) & 1) * OU_VS;
#pragma unroll
            for (int i = 0; i < 2; i++) {
                int row = p_row + i * 32;
                cp16(&dP[(size_t)row * 36 + p_k4], &P[(size_t)row * BAND + kb + p_k4], 16);
            }
#pragma unroll
            for (int i = 0; i < 4; i++) {
                int kr = v_kr + i * 8;
                int jg = t0 - HALF_W + kb + kr;
                jg = max(0, min(S_LEN - 1, jg));
                cp16(&sV[((t + 1) & 1) * OU_VS + (size_t)kr * 132 + v_c4],
                     &V[(size_t)jg * D_MODEL + n0 + v_c4], 16);
                (void)dV;
            }
            cp_commit();
            cp_wait<1>();
        } else {
            cp_wait<0>();
        }
        __syncthreads();

        const unsigned* cP = sP + (t & 1) * OU_PS;
        const unsigned* cV = sV + (t & 1) * OU_VS;

#pragma unroll
        for (int ks = 0; ks < 4; ks++) {
            const int k0 = ks * 8;
            unsigned a[2][4], bfr[4][2];
#pragma unroll
            for (int mf = 0; mf < 2; mf++) {
                int m = warp_m * 32 + mf * 16 + g;
                a[mf][0] = cP[(size_t)m * 36 + k0 + tg];
                a[mf][1] = cP[(size_t)(m + 8) * 36 + k0 + tg];
                a[mf][2] = cP[(size_t)m * 36 + k0 + tg + 4];
                a[mf][3] = cP[(size_t)(m + 8) * 36 + k0 + tg + 4];
            }
#pragma unroll
            for (int nf = 0; nf < 4; nf++) {
                int n = warp_n * 32 + nf * 8 + g;
                bfr[nf][0] = cV[(size_t)(k0 + tg) * 132 + n];
                bfr[nf][1] = cV[(size_t)(k0 + tg + 4) * 132 + n];
            }
#pragma unroll
            for (int mf = 0; mf < 2; mf++)
#pragma unroll
                for (int nf = 0; nf < 4; nf++)
                    mma_tf32(acc[mf][nf], a[mf][0], a[mf][1], a[mf][2], a[mf][3],
                             bfr[nf][0], bfr[nf][1]);
        }
        __syncthreads();
    }

#pragma unroll
    for (int mf = 0; mf < 2; mf++) {
        int row0 = t0 + warp_m * 32 + mf * 16 + g;
#pragma unroll
        for (int nf = 0; nf < 4; nf++) {
            int col = n0 + warp_n * 32 + nf * 8 + 2 * tg;
            float2 o0, o1;
            o0.x = acc[mf][nf][0]; o0.y = acc[mf][nf][1];
            o1.x = acc[mf][nf][2]; o1.y = acc[mf][nf][3];
            *(float2*)&out[((size_t)b * S_LEN + row0) * D_MODEL + col] = o0;
            *(float2*)&out[((size_t)b * S_LEN + row0 + 8) * D_MODEL + col] = o1;
        }
    }
}

// =====================================================================
extern "C" void kernel_launch(void* const* d_in, const int* in_sizes, int n_in,
                              void* d_out, int out_size)
{
    const float* x  = (const float*)d_in[0];
    const float* Wq = (const float*)d_in[1];
    const float* bq = (const float*)d_in[2];
    const float* Wk = (const float*)d_in[3];
    const float* bk = (const float*)d_in[4];
    const float* Wv = (const float*)d_in[5];
    const float* bv = (const float*)d_in[6];
    float* out = (float*)d_out;

    cudaFuncSetAttribute(qkv_mma, cudaFuncAttributeMaxDynamicSharedMemorySize, QKV_SMEM);
    cudaFuncSetAttribute(scores_mma, cudaFuncAttributeMaxDynamicSharedMemorySize, SC_SMEM);
    cudaFuncSetAttribute(out_mma, cudaFuncAttributeMaxDynamicSharedMemorySize, OU_SMEM);

    // prepass: pack operands in fragment order (tf32-rounded)
    pack_x<<<(MT_ALL * KT_ALL * 32) / 256, 256>>>(x);
    pack_w<<<dim3((NT_ALL * KT_ALL * 32) / 256, 3), 256>>>(Wq, Wk, Wv);

    qkv_mma<<<dim3(D_MODEL / 128, M_ALL / 128, 3), 256, QKV_SMEM>>>(bq, bk, bv);

    scores_mma<<<dim3(NTILES, B_BATCH), 256, SC_SMEM>>>();

    out_mma<<<dim3(D_MODEL / 128, NTILES, B_BATCH), 256, OU_SMEM>>>(out);
}

// round 11
// speedup vs baseline: 3.9711x; 1.0850x over previous
#include <cuda_runtime.h>
#include <math.h>
#include <stdint.h>

#define B_BATCH 4
#define S_LEN   4096
#define D_MODEL 512
#define HALF_W  128
#define BAND    320
#define NTILES  (S_LEN / 64)

#define M_ALL   (B_BATCH * S_LEN)          // 16384 rows
#define MT_ALL  (M_ALL / 16)               // 1024 m-tiles
#define JT_ALL  (M_ALL / 8)                // 2048 key-tiles (512 per batch)
#define KT_ALL  (D_MODEL / 8)              // 64 k-tiles
#define NT_ALL  (D_MODEL / 8)              // 64 n-tiles
#define WP_SZ   ((size_t)NT_ALL * KT_ALL * 32 * 2)

// ---------------- device scratch (no allocations allowed) ----------------
__device__ float g_P[(size_t)B_BATCH * NTILES * 64 * BAND];
__device__ float g_Xp[(size_t)MT_ALL * KT_ALL * 32 * 4];   // a-frag-packed x (tf32)
__device__ float g_Wp[3][WP_SZ];                           // b-frag-packed W (tf32)
__device__ float g_Qp[(size_t)MT_ALL * KT_ALL * 32 * 4];   // a-frag-packed Q (pre-scaled)
__device__ float g_Kp[(size_t)JT_ALL * KT_ALL * 32 * 2];   // b-frag-packed K (n=key, k=d)
__device__ float g_Vp[(size_t)JT_ALL * NT_ALL * 32 * 2];   // b-frag-packed V (k=key, n=d)

// ---------------- helpers ----------------
__device__ __forceinline__ unsigned f2tf(float f) {
    unsigned r;
    asm("cvt.rna.tf32.f32 %0, %1;" : "=r"(r) : "f"(f));
    return r;
}

__device__ __forceinline__ void mma_tf32(float c[4],
                                         unsigned a0, unsigned a1, unsigned a2, unsigned a3,
                                         unsigned b0, unsigned b1) {
    asm volatile(
        "mma.sync.aligned.m16n8k8.row.col.f32.tf32.tf32.f32 "
        "{%0,%1,%2,%3}, {%4,%5,%6,%7}, {%8,%9}, {%0,%1,%2,%3};\n"
        : "+f"(c[0]), "+f"(c[1]), "+f"(c[2]), "+f"(c[3])
        : "r"(a0), "r"(a1), "r"(a2), "r"(a3), "r"(b0), "r"(b1));
}

__device__ __forceinline__ void cp16(void* dst_smem, const void* src, int szbytes) {
    unsigned d = (unsigned)__cvta_generic_to_shared(dst_smem);
    asm volatile("cp.async.cg.shared.global [%0], [%1], 16, %2;\n"
                 :: "r"(d), "l"(src), "r"(szbytes));
}
__device__ __forceinline__ void cp_commit() {
    asm volatile("cp.async.commit_group;\n");
}
template <int N> __device__ __forceinline__ void cp_wait() {
    asm volatile("cp.async.wait_group %0;\n" :: "n"(N));
}

// =====================================================================
// Kernel 0a: pack x into a-fragment order (tf32-rounded).
// =====================================================================
__global__ __launch_bounds__(256) void pack_x(const float* __restrict__ x)
{
    int c = blockIdx.x * blockDim.x + threadIdx.x;
    const int total = MT_ALL * KT_ALL * 32;
    if (c >= total) return;
    int lane = c & 31;
    int kt = (c >> 5) & (KT_ALL - 1);
    int mt = c >> 11;
    int g = lane >> 2, tg = lane & 3;
    const float* p = x + (size_t)(mt * 16 + g) * D_MODEL + kt * 8 + tg;
    uint4 u;
    u.x = f2tf(p[0]);
    u.y = f2tf(p[8 * D_MODEL]);
    u.z = f2tf(p[4]);
    u.w = f2tf(p[8 * D_MODEL + 4]);
    *(uint4*)&g_Xp[(size_t)c * 4] = u;
}

// =====================================================================
// Kernel 0b: pack W into b-fragment order (tf32-rounded).
// =====================================================================
__global__ __launch_bounds__(256) void pack_w(
    const float* __restrict__ Wq, const float* __restrict__ Wk, const float* __restrict__ Wv)
{
    const float* src = (blockIdx.y == 0) ? Wq : (blockIdx.y == 1) ? Wk : Wv;
    float* dst = g_Wp[blockIdx.y];
    int c = blockIdx.x * blockDim.x + threadIdx.x;
    const int total = NT_ALL * KT_ALL * 32;
    if (c >= total) return;
    int lane = c & 31;
    int kt = (c >> 5) & (KT_ALL - 1);
    int nt = c >> 11;
    int g = lane >> 2, tg = lane & 3;
    const float* p = src + (size_t)(kt * 8 + tg) * D_MODEL + nt * 8 + g;
    float2 o;
    o.x = __uint_as_float(f2tf(p[0]));
    o.y = __uint_as_float(f2tf(p[4 * D_MODEL]));
    *(float2*)&dst[(size_t)c * 2] = o;
}

// =====================================================================
// Kernel 1: QKV projection, tf32 MMA, fragment-packed in AND out.
// Block 128x128, BK=32, 256 thr (8 warps 2m x 4n), warp 64x32.
// Epilogue stages half-tiles through smem (stride 132) and emits
// Q as a-frags, K/V as b-frags (coalesced STG.128 / STG.64).
// =====================================================================
#define QKV_AS  4096
#define QKV_BS  4096
#define QKV_SMEM ((2 * QKV_AS + 2 * QKV_BS) * 4)   // 65536 B

__global__ __launch_bounds__(256, 2) void qkv_mma(
    const float* __restrict__ bq, const float* __restrict__ bk, const float* __restrict__ bv)
{
    extern __shared__ float smem[];
    float* sA = smem;                  // [2][8 mt][4 kt][32 lane][4]
    float* sB = smem + 2 * QKV_AS;     // [2][16 nt][4 kt][32 lane][2]

    const int z = blockIdx.z;
    const float* Wp   = g_Wp[z];
    const float* bias = (z == 0) ? bq : (z == 1) ? bk : bv;
    const float oscale = (z == 0) ? 0.044194173824159216f : 1.0f;

    const int m0 = blockIdx.y * 128;
    const int n0 = blockIdx.x * 128;
    const int mt0 = m0 >> 4;
    const int nt0 = n0 >> 3;
    const int tid = threadIdx.x;
    const int warp = tid >> 5;
    const int lane = tid & 31;
    const int warp_m = warp >> 2;       // 0..1
    const int warp_n = warp & 3;        // 0..3
    const int g  = lane >> 2;
    const int tg = lane & 3;

    float acc[4][4][4];
#pragma unroll
    for (int mf = 0; mf < 4; mf++)
#pragma unroll
        for (int nf = 0; nf < 4; nf++)
#pragma unroll
            for (int c = 0; c < 4; c++) acc[mf][nf][c] = 0.f;

    const int T = D_MODEL / 32;   // 16 stages

    auto load_stage = [&](int s) {
        float* dA = sA + (s & 1) * QKV_AS;
        float* dB = sB + (s & 1) * QKV_BS;
        const int ktb = s * 4;
#pragma unroll
        for (int i = 0; i < 4; i++) {
            int c = i * 256 + tid;
            int mt = c >> 7;
            int kt = (c >> 5) & 3;
            int ln = c & 31;
            cp16(&dA[((mt * 4 + kt) * 32 + ln) * 4],
                 &g_Xp[(((size_t)(mt0 + mt) * KT_ALL + ktb + kt) * 32 + ln) * 4], 16);
        }
#pragma unroll
        for (int i = 0; i < 4; i++) {
            int c = i * 256 + tid;
            int nt = c >> 6;
            int kt = (c >> 4) & 3;
            int pr = c & 15;
            cp16(&dB[(nt * 4 + kt) * 64 + pr * 4],
                 &Wp[(((size_t)(nt0 + nt) * KT_ALL + ktb + kt) * 32) * 2 + pr * 4], 16);
        }
        cp_commit();
    };

    load_stage(0);

    for (int t = 0; t < T; t++) {
        if (t + 1 < T) {
            load_stage(t + 1);
            cp_wait<1>();
        } else {
            cp_wait<0>();
        }
        __syncthreads();

        const float* cA = sA + (t & 1) * QKV_AS;
        const float* cB = sB + (t & 1) * QKV_BS;

#pragma unroll
        for (int ks = 0; ks < 4; ks++) {
            uint4 a[4];
            uint2 b[4];
#pragma unroll
            for (int mf = 0; mf < 4; mf++)
                a[mf] = *(const uint4*)&cA[(((warp_m * 4 + mf) * 4 + ks) * 32 + lane) * 4];
#pragma unroll
            for (int nf = 0; nf < 4; nf++)
                b[nf] = *(const uint2*)&cB[((warp_n * 4 + nf) * 4 + ks) * 64 + lane * 2];
#pragma unroll
            for (int mf = 0; mf < 4; mf++)
#pragma unroll
                for (int nf = 0; nf < 4; nf++)
                    mma_tf32(acc[mf][nf], a[mf].x, a[mf].y, a[mf].z, a[mf].w,
                             b[nf].x, b[nf].y);
        }
        __syncthreads();
    }

    // ---- epilogue: stage half-tiles (64x132) through smem, emit packed ----
    float* st = smem;
    for (int p = 0; p < 2; p++) {
        __syncthreads();
        if (warp_m == p) {
#pragma unroll
            for (int mf = 0; mf < 4; mf++) {
                int rl = mf * 16 + g;
#pragma unroll
                for (int nf = 0; nf < 4; nf++) {
                    int cl = warp_n * 32 + nf * 8 + 2 * tg;
                    float2 bv = *(const float2*)&bias[n0 + cl];
                    st[rl * 132 + cl]           = __uint_as_float(f2tf((acc[mf][nf][0] + bv.x) * oscale));
                    st[rl * 132 + cl + 1]       = __uint_as_float(f2tf((acc[mf][nf][1] + bv.y) * oscale));
                    st[(rl + 8) * 132 + cl]     = __uint_as_float(f2tf((acc[mf][nf][2] + bv.x) * oscale));
                    st[(rl + 8) * 132 + cl + 1] = __uint_as_float(f2tf((acc[mf][nf][3] + bv.y) * oscale));
                }
            }
        }
        __syncthreads();

        const int rowbase = m0 + p * 64;
        if (z == 0) {
            // Q a-frag: 4 mt x 16 kt x 32 lanes -> 2048 chunks, 8/thread
#pragma unroll
            for (int i = 0; i < 8; i++) {
                int c = i * 256 + tid;
                int mt = c >> 9;
                int kt = (c >> 5) & 15;
                int ln = c & 31;
                int lg = ln >> 2, lt = ln & 3;
                float4 v;
                v.x = st[(mt * 16 + lg) * 132 + kt * 8 + lt];
                v.y = st[(mt * 16 + 8 + lg) * 132 + kt * 8 + lt];
                v.z = st[(mt * 16 + lg) * 132 + kt * 8 + lt + 4];
                v.w = st[(mt * 16 + 8 + lg) * 132 + kt * 8 + lt + 4];
                size_t mt_g = (size_t)(rowbase >> 4) + mt;
                size_t kt_g = (size_t)(n0 >> 3) + kt;
                *(float4*)&g_Qp[((mt_g * KT_ALL + kt_g) * 32 + ln) * 4] = v;
            }
        } else {
            float* dst = (z == 1) ? g_Kp : g_Vp;
            // K/V b-frag: 8 jt x 16 ct x 32 lanes -> 4096 chunks, 16/thread
#pragma unroll
            for (int i = 0; i < 16; i++) {
                int c = i * 256 + tid;
                int jt = c >> 9;
                int ct = (c >> 5) & 15;
                int ln = c & 31;
                int lg = ln >> 2, lt = ln & 3;
                float2 v;
                if (z == 1) {
                    // K: B(n=key,k=d): b0=K[key g][d tg], b1=K[key g][d tg+4]
                    v.x = st[(jt * 8 + lg) * 132 + ct * 8 + lt];
                    v.y = st[(jt * 8 + lg) * 132 + ct * 8 + lt + 4];
                } else {
                    // V: B(k=key,n=d): b0=V[key tg][d g], b1=V[key tg+4][d g]
                    v.x = st[(jt * 8 + lt) * 132 + ct * 8 + lg];
                    v.y = st[(jt * 8 + lt + 4) * 132 + ct * 8 + lg];
                }
                size_t jt_g = (size_t)(rowbase >> 3) + jt;
                size_t ct_g = (size_t)(n0 >> 3) + ct;
                *(float2*)&dst[((jt_g * KT_ALL + ct_g) * 32 + ln) * 2] = v;
            }
        }
    }
}

// =====================================================================
// Kernel 2: banded scores + softmax -> P, packed operands.
// Block 64q x 320-key band, BK=16 (2 k-tiles/stage), 2-stage cp.async.
// a-frags: 1 LDS.128, b-frags: 1 LDS.64.
// =====================================================================
#define SC_QS (4 * 2 * 32 * 4)     // 1024 floats/stage
#define SC_KS (40 * 2 * 32 * 2)    // 5120 floats/stage
#define SC_SMEM ((2 * SC_QS + 2 * SC_KS) * 4 + 64 * 8 * 4)   // 51200 B

__global__ __launch_bounds__(256) void scores_mma()
{
    extern __shared__ float smem[];
    float* sQ = smem;
    float* sK = smem + 2 * SC_QS;
    float* redm = smem + 2 * SC_QS + 2 * SC_KS;   // [64][4]
    float* reds = redm + 64 * 4;                   // [64][4]

    const int t0 = blockIdx.x * 64;
    const int b  = blockIdx.y;
    const int mt0 = b * 256 + (t0 >> 4);
    const int jtb = (t0 - HALF_W) / 8;             // first band key-tile (may be <0)
    float* P = g_P + ((size_t)(b * NTILES + blockIdx.x)) * 64 * BAND;

    const int tid = threadIdx.x;
    const int warp = tid >> 5;
    const int lane = tid & 31;
    const int warp_m = warp >> 2;
    const int warp_n = warp & 3;
    const int g  = lane >> 2;
    const int tg = lane & 3;

    float acc[2][10][4];
#pragma unroll
    for (int mf = 0; mf < 2; mf++)
#pragma unroll
        for (int nf = 0; nf < 10; nf++)
#pragma unroll
            for (int c = 0; c < 4; c++) acc[mf][nf][c] = 0.f;

    const int T = KT_ALL / 2;   // 32 stages

    auto load_stage = [&](int s) {
        float* dQ = sQ + (s & 1) * SC_QS;
        float* dK = sK + (s & 1) * SC_KS;
        const int ktb = s * 2;
        {
            int c = tid;                 // 256 chunks: mt(4) x kt(2) x lane(32)
            int mt = c >> 6;
            int kt = (c >> 5) & 1;
            int ln = c & 31;
            cp16(&dQ[((mt * 2 + kt) * 32 + ln) * 4],
                 &g_Qp[(((size_t)(mt0 + mt) * KT_ALL + ktb + kt) * 32 + ln) * 4], 16);
        }
#pragma unroll
        for (int i = 0; i < 5; i++) {    // 1280 chunks: jt(40) x kt(2) x pr(16)
            int c = i * 256 + tid;
            int jt = c >> 5;
            int kt = (c >> 4) & 1;
            int pr = c & 15;
            int jl = jtb + jt;
            jl = max(0, min(511, jl));   // clamp; OOB cols masked later
            size_t jt_g = (size_t)b * 512 + jl;
            cp16(&dK[((jt * 2 + kt) * 32 + pr * 2) * 2],
                 &g_Kp[((jt_g * KT_ALL + ktb + kt) * 32 + pr * 2) * 2], 16);
        }
        cp_commit();
    };

    load_stage(0);

    for (int t = 0; t < T; t++) {
        if (t + 1 < T) {
            load_stage(t + 1);
            cp_wait<1>();
        } else {
            cp_wait<0>();
        }
        __syncthreads();

        const float* cQ = sQ + (t & 1) * SC_QS;
        const float* cK = sK + (t & 1) * SC_KS;

#pragma unroll
        for (int ks = 0; ks < 2; ks++) {
            uint4 a[2];
            uint2 bfr[10];
#pragma unroll
            for (int mf = 0; mf < 2; mf++)
                a[mf] = *(const uint4*)&cQ[(((warp_m * 2 + mf) * 2 + ks) * 32 + lane) * 4];
#pragma unroll
            for (int nf = 0; nf < 10; nf++)
                bfr[nf] = *(const uint2*)&cK[(((warp_n * 10 + nf) * 2 + ks) * 32 + lane) * 2];
#pragma unroll
            for (int mf = 0; mf < 2; mf++)
#pragma unroll
                for (int nf = 0; nf < 10; nf++)
                    mma_tf32(acc[mf][nf], a[mf].x, a[mf].y, a[mf].z, a[mf].w,
                             bfr[nf].x, bfr[nf].y);
        }
        __syncthreads();
    }

    // ---------- masking + row max ----------
    float rmax[2][2];
#pragma unroll
    for (int mf = 0; mf < 2; mf++)
#pragma unroll
        for (int h = 0; h < 2; h++) rmax[mf][h] = -INFINITY;

#pragma unroll
    for (int mf = 0; mf < 2; mf++)
#pragma unroll
        for (int h = 0; h < 2; h++) {
            const int r = warp_m * 32 + mf * 16 + g + h * 8;
#pragma unroll
            for (int nf = 0; nf < 10; nf++)
#pragma unroll
                for (int cc = 0; cc < 2; cc++) {
                    int c = warp_n * 80 + nf * 8 + 2 * tg + cc;
                    int jg = t0 - HALF_W + c;
                    bool valid = (c >= r) && (c <= r + 2 * HALF_W) && (jg >= 0) && (jg < S_LEN);
                    float v = valid ? acc[mf][nf][h * 2 + cc] : -INFINITY;
                    acc[mf][nf][h * 2 + cc] = v;
                    rmax[mf][h] = fmaxf(rmax[mf][h], v);
                }
        }
#pragma unroll
    for (int mf = 0; mf < 2; mf++)
#pragma unroll
        for (int h = 0; h < 2; h++) {
            rmax[mf][h] = fmaxf(rmax[mf][h], __shfl_xor_sync(0xffffffffu, rmax[mf][h], 1));
            rmax[mf][h] = fmaxf(rmax[mf][h], __shfl_xor_sync(0xffffffffu, rmax[mf][h], 2));
        }
    if (tg == 0)
#pragma unroll
        for (int mf = 0; mf < 2; mf++)
#pragma unroll
            for (int h = 0; h < 2; h++)
                redm[(warp_m * 32 + mf * 16 + g + h * 8) * 4 + warp_n] = rmax[mf][h];
    __syncthreads();

    float gm[2][2];
#pragma unroll
    for (int mf = 0; mf < 2; mf++)
#pragma unroll
        for (int h = 0; h < 2; h++) {
            int r = warp_m * 32 + mf * 16 + g + h * 8;
            gm[mf][h] = fmaxf(fmaxf(redm[r * 4 + 0], redm[r * 4 + 1]),
                              fmaxf(redm[r * 4 + 2], redm[r * 4 + 3]));
        }

    // ---------- exp + row sum ----------
    float rsum[2][2] = {{0.f, 0.f}, {0.f, 0.f}};
#pragma unroll
    for (int mf = 0; mf < 2; mf++)
#pragma unroll
        for (int h = 0; h < 2; h++)
#pragma unroll
            for (int nf = 0; nf < 10; nf++)
#pragma unroll
                for (int cc = 0; cc < 2; cc++) {
                    float e = __expf(acc[mf][nf][h * 2 + cc] - gm[mf][h]);
                    acc[mf][nf][h * 2 + cc] = e;
                    rsum[mf][h] += e;
                }
#pragma unroll
    for (int mf = 0; mf < 2; mf++)
#pragma unroll
        for (int h = 0; h < 2; h++) {
            rsum[mf][h] += __shfl_xor_sync(0xffffffffu, rsum[mf][h], 1);
            rsum[mf][h] += __shfl_xor_sync(0xffffffffu, rsum[mf][h], 2);
        }
    if (tg == 0)
#pragma unroll
        for (int mf = 0; mf < 2; mf++)
#pragma unroll
            for (int h = 0; h < 2; h++)
                reds[(warp_m * 32 + mf * 16 + g + h * 8) * 4 + warp_n] = rsum[mf][h];
    __syncthreads();

#pragma unroll
    for (int mf = 0; mf < 2; mf++)
#pragma unroll
        for (int h = 0; h < 2; h++) {
            int r = warp_m * 32 + mf * 16 + g + h * 8;
            float s = reds[r * 4 + 0] + reds[r * 4 + 1] + reds[r * 4 + 2] + reds[r * 4 + 3];
            float inv = 1.0f / s;
#pragma unroll
            for (int nf = 0; nf < 10; nf++) {
                int c = warp_n * 80 + nf * 8 + 2 * tg;
                float2 o;
                o.x = __uint_as_float(f2tf(acc[mf][nf][h * 2 + 0] * inv));
                o.y = __uint_as_float(f2tf(acc[mf][nf][h * 2 + 1] * inv));
                *(float2*)&P[(size_t)r * BAND + c] = o;
            }
        }
}

// =====================================================================
// Kernel 3: O = P @ V_band. P row-major (smem 36-pad), V fragment-packed.
// Block 64x128, K=320 band, BK=32 (4 key-tiles/stage).
// =====================================================================
#define OU_PS (64 * 36)            // 2304 floats/stage
#define OU_VS (4 * 16 * 32 * 2)    // 4096 floats/stage
#define OU_SMEM ((2 * OU_PS + 2 * OU_VS) * 4)   // 51200 B

__global__ __launch_bounds__(256, 2) void out_mma(float* __restrict__ out)
{
    extern __shared__ float smem[];
    float* sP = smem;
    float* sV = smem + 2 * OU_PS;

    const int n0   = blockIdx.x * 128;
    const int nt0  = n0 >> 3;
    const int tile = blockIdx.y;
    const int b    = blockIdx.z;
    const int t0   = tile * 64;

    const float* P = g_P + ((size_t)(b * NTILES + tile)) * 64 * BAND;

    const int tid = threadIdx.x;
    const int warp = tid >> 5;
    const int lane = tid & 31;
    const int warp_m = warp >> 2;
    const int warp_n = warp & 3;
    const int g  = lane >> 2;
    const int tg = lane & 3;

    const int p_row = tid >> 3;
    const int p_k4  = (tid & 7) * 4;

    float acc[2][4][4];
#pragma unroll
    for (int mf = 0; mf < 2; mf++)
#pragma unroll
        for (int nf = 0; nf < 4; nf++)
#pragma unroll
            for (int c = 0; c < 4; c++) acc[mf][nf][c] = 0.f;

    const int T = BAND / 32;   // 10 stages

    auto load_stage = [&](int s) {
        float* dP = sP + (s & 1) * OU_PS;
        float* dV = sV + (s & 1) * OU_VS;
        const int kb = s * 32;
#pragma unroll
        for (int i = 0; i < 2; i++) {   // P 64x32: 512 chunks
            int row = p_row + i * 32;
            cp16(&dP[(size_t)row * 36 + p_k4], &P[(size_t)row * BAND + kb + p_k4], 16);
        }
#pragma unroll
        for (int i = 0; i < 4; i++) {   // V: kt(4) x nt(16) x pr(16) = 1024 chunks
            int c = i * 256 + tid;
            int kt = c >> 8;
            int nt = (c >> 4) & 15;
            int pr = c & 15;
            int jl = (t0 - HALF_W + kb) / 8 + kt;   // band key-tile
            jl = max(0, min(511, jl));              // clamp; P==0 for OOB keys
            size_t jt_g = (size_t)b * 512 + jl;
            cp16(&dV[((kt * 16 + nt) * 32 + pr * 2) * 2],
                 &g_Vp[((jt_g * KT_ALL + nt0 + nt) * 32 + pr * 2) * 2], 16);
        }
        cp_commit();
    };

    load_stage(0);

    for (int t = 0; t < T; t++) {
        if (t + 1 < T) {
            load_stage(t + 1);
            cp_wait<1>();
        } else {
            cp_wait<0>();
        }
        __syncthreads();

        const float* cP = sP + (t & 1) * OU_PS;
        const float* cV = sV + (t & 1) * OU_VS;

#pragma unroll
        for (int ks = 0; ks < 4; ks++) {
            const int k0 = ks * 8;
            unsigned a[2][4];
            uint2 bfr[4];
#pragma unroll
            for (int mf = 0; mf < 2; mf++) {
                int m = warp_m * 32 + mf * 16 + g;
                a[mf][0] = __float_as_uint(cP[(size_t)m * 36 + k0 + tg]);
                a[mf][1] = __float_as_uint(cP[(size_t)(m + 8) * 36 + k0 + tg]);
                a[mf][2] = __float_as_uint(cP[(size_t)m * 36 + k0 + tg + 4]);
                a[mf][3] = __float_as_uint(cP[(size_t)(m + 8) * 36 + k0 + tg + 4]);
            }
#pragma unroll
            for (int nf = 0; nf < 4; nf++)
                bfr[nf] = *(const uint2*)&cV[((ks * 16 + warp_n * 4 + nf) * 32 + lane) * 2];
#pragma unroll
            for (int mf = 0; mf < 2; mf++)
#pragma unroll
                for (int nf = 0; nf < 4; nf++)
                    mma_tf32(acc[mf][nf], a[mf][0], a[mf][1], a[mf][2], a[mf][3],
                             bfr[nf].x, bfr[nf].y);
        }
        __syncthreads();
    }

#pragma unroll
    for (int mf = 0; mf < 2; mf++) {
        int row0 = t0 + warp_m * 32 + mf * 16 + g;
#pragma unroll
        for (int nf = 0; nf < 4; nf++) {
            int col = n0 + warp_n * 32 + nf * 8 + 2 * tg;
            float2 o0, o1;
            o0.x = acc[mf][nf][0]; o0.y = acc[mf][nf][1];
            o1.x = acc[mf][nf][2]; o1.y = acc[mf][nf][3];
            *(float2*)&out[((size_t)b * S_LEN + row0) * D_MODEL + col] = o0;
            *(float2*)&out[((size_t)b * S_LEN + row0 + 8) * D_MODEL + col] = o1;
        }
    }
}

// =====================================================================
extern "C" void kernel_launch(void* const* d_in, const int* in_sizes, int n_in,
                              void* d_out, int out_size)
{
    const float* x  = (const float*)d_in[0];
    const float* Wq = (const float*)d_in[1];
    const float* bq = (const float*)d_in[2];
    const float* Wk = (const float*)d_in[3];
    const float* bk = (const float*)d_in[4];
    const float* Wv = (const float*)d_in[5];
    const float* bv = (const float*)d_in[6];
    float* out = (float*)d_out;

    cudaFuncSetAttribute(qkv_mma, cudaFuncAttributeMaxDynamicSharedMemorySize, QKV_SMEM);
    cudaFuncSetAttribute(scores_mma, cudaFuncAttributeMaxDynamicSharedMemorySize, SC_SMEM);
    cudaFuncSetAttribute(out_mma, cudaFuncAttributeMaxDynamicSharedMemorySize, OU_SMEM);

    pack_x<<<(MT_ALL * KT_ALL * 32) / 256, 256>>>(x);
    pack_w<<<dim3((NT_ALL * KT_ALL * 32) / 256, 3), 256>>>(Wq, Wk, Wv);

    qkv_mma<<<dim3(D_MODEL / 128, M_ALL / 128, 3), 256, QKV_SMEM>>>(bq, bk, bv);

    scores_mma<<<dim3(NTILES, B_BATCH), 256, SC_SMEM>>>();

    out_mma<<<dim3(D_MODEL / 128, NTILES, B_BATCH), 256, OU_SMEM>>>(out);
}

// round 14
// speedup vs baseline: 4.0092x; 1.0096x over previous
#include <cuda_runtime.h>
#include <math.h>
#include <stdint.h>

#define B_BATCH 4
#define S_LEN   4096
#define D_MODEL 512
#define HALF_W  128
#define BAND    320
#define NTILES  (S_LEN / 64)

#define M_ALL   (B_BATCH * S_LEN)          // 16384 rows
#define MT_ALL  (M_ALL / 16)               // 1024 m-tiles
#define JT_ALL  (M_ALL / 8)                // 2048 key-tiles (512 per batch)
#define KT_ALL  (D_MODEL / 8)              // 64 k-tiles
#define NT_ALL  (D_MODEL / 8)              // 64 n-tiles
#define WP_SZ   ((size_t)NT_ALL * KT_ALL * 32 * 2)

// ---------------- device scratch (no allocations allowed) ----------------
__device__ float g_Xp[(size_t)MT_ALL * KT_ALL * 32 * 4];   // a-frag-packed x (tf32)
__device__ float g_Wp[3][WP_SZ];                           // b-frag-packed W (tf32)
__device__ float g_Qp[(size_t)MT_ALL * KT_ALL * 32 * 4];   // a-frag-packed Q (pre-scaled)
__device__ float g_Kp[(size_t)JT_ALL * KT_ALL * 32 * 2];   // b-frag-packed K (n=key, k=d)
__device__ float g_Vp[(size_t)JT_ALL * NT_ALL * 32 * 2];   // b-frag-packed V (k=key, n=d)

// ---------------- helpers ----------------
__device__ __forceinline__ unsigned f2tf(float f) {
    unsigned r;
    asm("cvt.rna.tf32.f32 %0, %1;" : "=r"(r) : "f"(f));
    return r;
}

__device__ __forceinline__ void mma_tf32(float c[4],
                                         unsigned a0, unsigned a1, unsigned a2, unsigned a3,
                                         unsigned b0, unsigned b1) {
    asm volatile(
        "mma.sync.aligned.m16n8k8.row.col.f32.tf32.tf32.f32 "
        "{%0,%1,%2,%3}, {%4,%5,%6,%7}, {%8,%9}, {%0,%1,%2,%3};\n"
        : "+f"(c[0]), "+f"(c[1]), "+f"(c[2]), "+f"(c[3])
        : "r"(a0), "r"(a1), "r"(a2), "r"(a3), "r"(b0), "r"(b1));
}

__device__ __forceinline__ void cp16(void* dst_smem, const void* src, int szbytes) {
    unsigned d = (unsigned)__cvta_generic_to_shared(dst_smem);
    asm volatile("cp.async.cg.shared.global [%0], [%1], 16, %2;\n"
                 :: "r"(d), "l"(src), "r"(szbytes));
}
__device__ __forceinline__ void cp_commit() {
    asm volatile("cp.async.commit_group;\n");
}
template <int N> __device__ __forceinline__ void cp_wait() {
    asm volatile("cp.async.wait_group %0;\n" :: "n"(N));
}

// =====================================================================
// Kernel 0a: pack x into a-fragment order (tf32-rounded).
// =====================================================================
__global__ __launch_bounds__(256) void pack_x(const float* __restrict__ x)
{
    int c = blockIdx.x * blockDim.x + threadIdx.x;
    const int total = MT_ALL * KT_ALL * 32;
    if (c >= total) return;
    int lane = c & 31;
    int kt = (c >> 5) & (KT_ALL - 1);
    int mt = c >> 11;
    int g = lane >> 2, tg = lane & 3;
    const float* p = x + (size_t)(mt * 16 + g) * D_MODEL + kt * 8 + tg;
    uint4 u;
    u.x = f2tf(p[0]);
    u.y = f2tf(p[8 * D_MODEL]);
    u.z = f2tf(p[4]);
    u.w = f2tf(p[8 * D_MODEL + 4]);
    *(uint4*)&g_Xp[(size_t)c * 4] = u;
}

// =====================================================================
// Kernel 0b: pack W into b-fragment order (tf32-rounded).
// =====================================================================
__global__ __launch_bounds__(256) void pack_w(
    const float* __restrict__ Wq, const float* __restrict__ Wk, const float* __restrict__ Wv)
{
    const float* src = (blockIdx.y == 0) ? Wq : (blockIdx.y == 1) ? Wk : Wv;
    float* dst = g_Wp[blockIdx.y];
    int c = blockIdx.x * blockDim.x + threadIdx.x;
    const int total = NT_ALL * KT_ALL * 32;
    if (c >= total) return;
    int lane = c & 31;
    int kt = (c >> 5) & (KT_ALL - 1);
    int nt = c >> 11;
    int g = lane >> 2, tg = lane & 3;
    const float* p = src + (size_t)(kt * 8 + tg) * D_MODEL + nt * 8 + g;
    float2 o;
    o.x = __uint_as_float(f2tf(p[0]));
    o.y = __uint_as_float(f2tf(p[4 * D_MODEL]));
    *(float2*)&dst[(size_t)c * 2] = o;
}

// =====================================================================
// Kernel 1: QKV projection, tf32 MMA, fragment-packed in AND out.
// (unchanged from passing R11 version)
// =====================================================================
#define QKV_AS  4096
#define QKV_BS  4096
#define QKV_SMEM ((2 * QKV_AS + 2 * QKV_BS) * 4)   // 65536 B

__global__ __launch_bounds__(256, 2) void qkv_mma(
    const float* __restrict__ bq, const float* __restrict__ bk, const float* __restrict__ bv)
{
    extern __shared__ float smem[];
    float* sA = smem;                  // [2][8 mt][4 kt][32 lane][4]
    float* sB = smem + 2 * QKV_AS;     // [2][16 nt][4 kt][32 lane][2]

    const int z = blockIdx.z;
    const float* Wp   = g_Wp[z];
    const float* bias = (z == 0) ? bq : (z == 1) ? bk : bv;
    const float oscale = (z == 0) ? 0.044194173824159216f : 1.0f;

    const int m0 = blockIdx.y * 128;
    const int n0 = blockIdx.x * 128;
    const int mt0 = m0 >> 4;
    const int nt0 = n0 >> 3;
    const int tid = threadIdx.x;
    const int warp = tid >> 5;
    const int lane = tid & 31;
    const int warp_m = warp >> 2;       // 0..1
    const int warp_n = warp & 3;        // 0..3
    const int g  = lane >> 2;
    const int tg = lane & 3;

    float acc[4][4][4];
#pragma unroll
    for (int mf = 0; mf < 4; mf++)
#pragma unroll
        for (int nf = 0; nf < 4; nf++)
#pragma unroll
            for (int c = 0; c < 4; c++) acc[mf][nf][c] = 0.f;

    const int T = D_MODEL / 32;   // 16 stages

    auto load_stage = [&](int s) {
        float* dA = sA + (s & 1) * QKV_AS;
        float* dB = sB + (s & 1) * QKV_BS;
        const int ktb = s * 4;
#pragma unroll
        for (int i = 0; i < 4; i++) {
            int c = i * 256 + tid;
            int mt = c >> 7;
            int kt = (c >> 5) & 3;
            int ln = c & 31;
            cp16(&dA[((mt * 4 + kt) * 32 + ln) * 4],
                 &g_Xp[(((size_t)(mt0 + mt) * KT_ALL + ktb + kt) * 32 + ln) * 4], 16);
        }
#pragma unroll
        for (int i = 0; i < 4; i++) {
            int c = i * 256 + tid;
            int nt = c >> 6;
            int kt = (c >> 4) & 3;
            int pr = c & 15;
            cp16(&dB[(nt * 4 + kt) * 64 + pr * 4],
                 &Wp[(((size_t)(nt0 + nt) * KT_ALL + ktb + kt) * 32) * 2 + pr * 4], 16);
        }
        cp_commit();
    };

    load_stage(0);

    for (int t = 0; t < T; t++) {
        if (t + 1 < T) {
            load_stage(t + 1);
            cp_wait<1>();
        } else {
            cp_wait<0>();
        }
        __syncthreads();

        const float* cA = sA + (t & 1) * QKV_AS;
        const float* cB = sB + (t & 1) * QKV_BS;

#pragma unroll
        for (int ks = 0; ks < 4; ks++) {
            uint4 a[4];
            uint2 b[4];
#pragma unroll
            for (int mf = 0; mf < 4; mf++)
                a[mf] = *(const uint4*)&cA[(((warp_m * 4 + mf) * 4 + ks) * 32 + lane) * 4];
#pragma unroll
            for (int nf = 0; nf < 4; nf++)
                b[nf] = *(const uint2*)&cB[((warp_n * 4 + nf) * 4 + ks) * 64 + lane * 2];
#pragma unroll
            for (int mf = 0; mf < 4; mf++)
#pragma unroll
                for (int nf = 0; nf < 4; nf++)
                    mma_tf32(acc[mf][nf], a[mf].x, a[mf].y, a[mf].z, a[mf].w,
                             b[nf].x, b[nf].y);
        }
        __syncthreads();
    }

    // ---- epilogue: stage half-tiles (64x132) through smem, emit packed ----
    float* st = smem;
    for (int p = 0; p < 2; p++) {
        __syncthreads();
        if (warp_m == p) {
#pragma unroll
            for (int mf = 0; mf < 4; mf++) {
                int rl = mf * 16 + g;
#pragma unroll
                for (int nf = 0; nf < 4; nf++) {
                    int cl = warp_n * 32 + nf * 8 + 2 * tg;
                    float2 bv = *(const float2*)&bias[n0 + cl];
                    st[rl * 132 + cl]           = __uint_as_float(f2tf((acc[mf][nf][0] + bv.x) * oscale));
                    st[rl * 132 + cl + 1]       = __uint_as_float(f2tf((acc[mf][nf][1] + bv.y) * oscale));
                    st[(rl + 8) * 132 + cl]     = __uint_as_float(f2tf((acc[mf][nf][2] + bv.x) * oscale));
                    st[(rl + 8) * 132 + cl + 1] = __uint_as_float(f2tf((acc[mf][nf][3] + bv.y) * oscale));
                }
            }
        }
        __syncthreads();

        const int rowbase = m0 + p * 64;
        if (z == 0) {
            // Q a-frag: 4 mt x 16 kt x 32 lanes -> 2048 chunks, 8/thread
#pragma unroll
            for (int i = 0; i < 8; i++) {
                int c = i * 256 + tid;
                int mt = c >> 9;
                int kt = (c >> 5) & 15;
                int ln = c & 31;
                int lg = ln >> 2, lt = ln & 3;
                float4 v;
                v.x = st[(mt * 16 + lg) * 132 + kt * 8 + lt];
                v.y = st[(mt * 16 + 8 + lg) * 132 + kt * 8 + lt];
                v.z = st[(mt * 16 + lg) * 132 + kt * 8 + lt + 4];
                v.w = st[(mt * 16 + 8 + lg) * 132 + kt * 8 + lt + 4];
                size_t mt_g = (size_t)(rowbase >> 4) + mt;
                size_t kt_g = (size_t)(n0 >> 3) + kt;
                *(float4*)&g_Qp[((mt_g * KT_ALL + kt_g) * 32 + ln) * 4] = v;
            }
        } else {
            float* dst = (z == 1) ? g_Kp : g_Vp;
            // K/V b-frag: 8 jt x 16 ct x 32 lanes -> 4096 chunks, 16/thread
#pragma unroll
            for (int i = 0; i < 16; i++) {
                int c = i * 256 + tid;
                int jt = c >> 9;
                int ct = (c >> 5) & 15;
                int ln = c & 31;
                int lg = ln >> 2, lt = ln & 3;
                float2 v;
                if (z == 1) {
                    v.x = st[(jt * 8 + lg) * 132 + ct * 8 + lt];
                    v.y = st[(jt * 8 + lg) * 132 + ct * 8 + lt + 4];
                } else {
                    v.x = st[(jt * 8 + lt) * 132 + ct * 8 + lg];
                    v.y = st[(jt * 8 + lt + 4) * 132 + ct * 8 + lg];
                }
                size_t jt_g = (size_t)(rowbase >> 3) + jt;
                size_t ct_g = (size_t)(n0 >> 3) + ct;
                *(float2*)&dst[((jt_g * KT_ALL + ct_g) * 32 + ln) * 2] = v;
            }
        }
    }
}

// =====================================================================
// Kernel 2: FUSED attention: scores + softmax -> P (smem) -> O = P @ V.
// Block = 64 queries x full 320-key band, all 512 output cols.
// Phase 1 == R11 scores_mma mainloop; P kept in smem [64][324] (tf32).
// Phase 2 == R11 out_mma mainloop reading P from smem, 4 n-chunks of 128.
// Smem: Q(2x1024) + K(2x5120) overlaid by P(20736); V(2x2048); red(512).
// Total 25344 floats = 101376 B -> occupancy 2.
// =====================================================================
#define F_QS 1024
#define F_KS 5120
#define F_PS (64 * 324)            // 20736
#define F_VS 2048
#define FU_SMEM ((F_PS + 2 * F_VS + 512) * 4)   // 101376 B

__global__ __launch_bounds__(256, 2) void attn_fused(float* __restrict__ out)
{
    extern __shared__ float smem[];
    float* sQ = smem;                      // [2][F_QS]   (phase 1 only)
    float* sK = smem + 2 * F_QS;           // [2][F_KS]   (phase 1 only)
    float* sP = smem;                      // [64][324]   (overlays sQ/sK after phase 1)
    float* sV = smem + F_PS;               // [2][F_VS]
    float* redm = smem + F_PS + 2 * F_VS;  // [64][4]
    float* reds = redm + 64 * 4;           // [64][4]

    const int t0 = blockIdx.x * 64;
    const int b  = blockIdx.y;
    const int mt0 = b * 256 + (t0 >> 4);
    const int jtb = (t0 - HALF_W) / 8;     // first band key-tile (exact: multiples of 8)

    const int tid = threadIdx.x;
    const int warp = tid >> 5;
    const int lane = tid & 31;
    const int warp_m = warp >> 2;
    const int warp_n = warp & 3;
    const int g  = lane >> 2;
    const int tg = lane & 3;

    // ---------------- phase 1: scores ----------------
    float acc[2][10][4];
#pragma unroll
    for (int mf = 0; mf < 2; mf++)
#pragma unroll
        for (int nf = 0; nf < 10; nf++)
#pragma unroll
            for (int c = 0; c < 4; c++) acc[mf][nf][c] = 0.f;

    const int T1 = KT_ALL / 2;   // 32 stages

    auto load_qk = [&](int s) {
        float* dQ = sQ + (s & 1) * F_QS;
        float* dK = sK + (s & 1) * F_KS;
        const int ktb = s * 2;
        {
            int c = tid;
            int mt = c >> 6;
            int kt = (c >> 5) & 1;
            int ln = c & 31;
            cp16(&dQ[((mt * 2 + kt) * 32 + ln) * 4],
                 &g_Qp[(((size_t)(mt0 + mt) * KT_ALL + ktb + kt) * 32 + ln) * 4], 16);
        }
#pragma unroll
        for (int i = 0; i < 5; i++) {
            int c = i * 256 + tid;
            int jt = c >> 5;
            int kt = (c >> 4) & 1;
            int pr = c & 15;
            int jl = jtb + jt;
            jl = max(0, min(511, jl));
            size_t jt_g = (size_t)b * 512 + jl;
            cp16(&dK[((jt * 2 + kt) * 32 + pr * 2) * 2],
                 &g_Kp[((jt_g * KT_ALL + ktb + kt) * 32 + pr * 2) * 2], 16);
        }
        cp_commit();
    };

    load_qk(0);

    for (int t = 0; t < T1; t++) {
        if (t + 1 < T1) {
            load_qk(t + 1);
            cp_wait<1>();
        } else {
            cp_wait<0>();
        }
        __syncthreads();

        const float* cQ = sQ + (t & 1) * F_QS;
        const float* cK = sK + (t & 1) * F_KS;

#pragma unroll
        for (int ks = 0; ks < 2; ks++) {
            uint4 a[2];
            uint2 bfr[10];
#pragma unroll
            for (int mf = 0; mf < 2; mf++)
                a[mf] = *(const uint4*)&cQ[(((warp_m * 2 + mf) * 2 + ks) * 32 + lane) * 4];
#pragma unroll
            for (int nf = 0; nf < 10; nf++)
                bfr[nf] = *(const uint2*)&cK[(((warp_n * 10 + nf) * 2 + ks) * 32 + lane) * 2];
#pragma unroll
            for (int mf = 0; mf < 2; mf++)
#pragma unroll
                for (int nf = 0; nf < 10; nf++)
                    mma_tf32(acc[mf][nf], a[mf].x, a[mf].y, a[mf].z, a[mf].w,
                             bfr[nf].x, bfr[nf].y);
        }
        __syncthreads();
    }

    // V flat-stage indexing for phase 2: f = nc*20 + s; nc = n-chunk (128 cols),
    // s = 16-key stage within band.
    auto load_v = [&](int f) {
        int nc = f / 20;
        int s  = f - nc * 20;
        float* dV = sV + (f & 1) * F_VS;
#pragma unroll
        for (int i = 0; i < 2; i++) {
            int c = i * 256 + tid;
            int kt = c >> 8;            // 0..1
            int nt = (c >> 4) & 15;
            int pr = c & 15;
            int jl = jtb + 2 * s + kt;
            jl = max(0, min(511, jl));  // clamp; P==0 for OOB keys
            size_t jt_g = (size_t)b * 512 + jl;
            cp16(&dV[((kt * 16 + nt) * 32 + pr * 2) * 2],
                 &g_Vp[((jt_g * KT_ALL + nc * 16 + nt) * 32 + pr * 2) * 2], 16);
        }
        cp_commit();
    };

    // prefetch V flat stage 0 while doing softmax (targets sV, disjoint from P)
    load_v(0);

    // ---------------- masking + softmax (registers + red smem) ----------------
    float rmax[2][2];
#pragma unroll
    for (int mf = 0; mf < 2; mf++)
#pragma unroll
        for (int h = 0; h < 2; h++) rmax[mf][h] = -INFINITY;

#pragma unroll
    for (int mf = 0; mf < 2; mf++)
#pragma unroll
        for (int h = 0; h < 2; h++) {
            const int r = warp_m * 32 + mf * 16 + g + h * 8;
#pragma unroll
            for (int nf = 0; nf < 10; nf++)
#pragma unroll
                for (int cc = 0; cc < 2; cc++) {
                    int c = warp_n * 80 + nf * 8 + 2 * tg + cc;
                    int jg = t0 - HALF_W + c;
                    bool valid = (c >= r) && (c <= r + 2 * HALF_W) && (jg >= 0) && (jg < S_LEN);
                    float v = valid ? acc[mf][nf][h * 2 + cc] : -INFINITY;
                    acc[mf][nf][h * 2 + cc] = v;
                    rmax[mf][h] = fmaxf(rmax[mf][h], v);
                }
        }
#pragma unroll
    for (int mf = 0; mf < 2; mf++)
#pragma unroll
        for (int h = 0; h < 2; h++) {
            rmax[mf][h] = fmaxf(rmax[mf][h], __shfl_xor_sync(0xffffffffu, rmax[mf][h], 1));
            rmax[mf][h] = fmaxf(rmax[mf][h], __shfl_xor_sync(0xffffffffu, rmax[mf][h], 2));
        }
    if (tg == 0)
#pragma unroll
        for (int mf = 0; mf < 2; mf++)
#pragma unroll
            for (int h = 0; h < 2; h++)
                redm[(warp_m * 32 + mf * 16 + g + h * 8) * 4 + warp_n] = rmax[mf][h];
    __syncthreads();

    float gm[2][2];
#pragma unroll
    for (int mf = 0; mf < 2; mf++)
#pragma unroll
        for (int h = 0; h < 2; h++) {
            int r = warp_m * 32 + mf * 16 + g + h * 8;
            gm[mf][h] = fmaxf(fmaxf(redm[r * 4 + 0], redm[r * 4 + 1]),
                              fmaxf(redm[r * 4 + 2], redm[r * 4 + 3]));
        }

    float rsum[2][2] = {{0.f, 0.f}, {0.f, 0.f}};
#pragma unroll
    for (int mf = 0; mf < 2; mf++)
#pragma unroll
        for (int h = 0; h < 2; h++)
#pragma unroll
            for (int nf = 0; nf < 10; nf++)
#pragma unroll
                for (int cc = 0; cc < 2; cc++) {
                    float e = __expf(acc[mf][nf][h * 2 + cc] - gm[mf][h]);
                    acc[mf][nf][h * 2 + cc] = e;
                    rsum[mf][h] += e;
                }
#pragma unroll
    for (int mf = 0; mf < 2; mf++)
#pragma unroll
        for (int h = 0; h < 2; h++) {
            rsum[mf][h] += __shfl_xor_sync(0xffffffffu, rsum[mf][h], 1);
            rsum[mf][h] += __shfl_xor_sync(0xffffffffu, rsum[mf][h], 2);
        }
    if (tg == 0)
#pragma unroll
        for (int mf = 0; mf < 2; mf++)
#pragma unroll
            for (int h = 0; h < 2; h++)
                reds[(warp_m * 32 + mf * 16 + g + h * 8) * 4 + warp_n] = rsum[mf][h];
    __syncthreads();

    // P -> smem [64][324] (tf32-rounded, same numerics as gmem P path)
#pragma unroll
    for (int mf = 0; mf < 2; mf++)
#pragma unroll
        for (int h = 0; h < 2; h++) {
            int r = warp_m * 32 + mf * 16 + g + h * 8;
            float s = reds[r * 4 + 0] + reds[r * 4 + 1] + reds[r * 4 + 2] + reds[r * 4 + 3];
            float inv = 1.0f / s;
#pragma unroll
            for (int nf = 0; nf < 10; nf++) {
                int c = warp_n * 80 + nf * 8 + 2 * tg;
                float2 o;
                o.x = __uint_as_float(f2tf(acc[mf][nf][h * 2 + 0] * inv));
                o.y = __uint_as_float(f2tf(acc[mf][nf][h * 2 + 1] * inv));
                *(float2*)&sP[r * 324 + c] = o;
            }
        }
    __syncthreads();   // P visible to all warps before phase 2

    // ---------------- phase 2: O = P @ V (4 n-chunks of 128) ----------------
    for (int nc = 0; nc < 4; nc++) {
        float oacc[2][4][4];
#pragma unroll
        for (int mf = 0; mf < 2; mf++)
#pragma unroll
            for (int nf = 0; nf < 4; nf++)
#pragma unroll
                for (int c = 0; c < 4; c++) oacc[mf][nf][c] = 0.f;

        for (int t = 0; t < 20; t++) {
            int f = nc * 20 + t;
            if (f + 1 < 80) {
                load_v(f + 1);
                cp_wait<1>();
            } else {
                cp_wait<0>();
            }
            __syncthreads();

            const float* cV = sV + (f & 1) * F_VS;
            const int kb = t * 16;

#pragma unroll
            for (int ks = 0; ks < 2; ks++) {
                const int k0 = kb + ks * 8;
                unsigned a[2][4];
                uint2 bfr[4];
#pragma unroll
                for (int mf = 0; mf < 2; mf++) {
                    int m = warp_m * 32 + mf * 16 + g;
                    a[mf][0] = __float_as_uint(sP[m * 324 + k0 + tg]);
                    a[mf][1] = __float_as_uint(sP[(m + 8) * 324 + k0 + tg]);
                    a[mf][2] = __float_as_uint(sP[m * 324 + k0 + tg + 4]);
                    a[mf][3] = __float_as_uint(sP[(m + 8) * 324 + k0 + tg + 4]);
                }
#pragma unroll
                for (int nf = 0; nf < 4; nf++)
                    bfr[nf] = *(const uint2*)&cV[((ks * 16 + warp_n * 4 + nf) * 32 + lane) * 2];
#pragma unroll
                for (int mf = 0; mf < 2; mf++)
#pragma unroll
                    for (int nf = 0; nf < 4; nf++)
                        mma_tf32(oacc[mf][nf], a[mf][0], a[mf][1], a[mf][2], a[mf][3],
                                 bfr[nf].x, bfr[nf].y);
            }
            __syncthreads();
        }

        // store this n-chunk
#pragma unroll
        for (int mf = 0; mf < 2; mf++) {
            int row0 = t0 + warp_m * 32 + mf * 16 + g;
#pragma unroll
            for (int nf = 0; nf < 4; nf++) {
                int col = nc * 128 + warp_n * 32 + nf * 8 + 2 * tg;
                float2 o0, o1;
                o0.x = oacc[mf][nf][0]; o0.y = oacc[mf][nf][1];
                o1.x = oacc[mf][nf][2]; o1.y = oacc[mf][nf][3];
                *(float2*)&out[((size_t)b * S_LEN + row0) * D_MODEL + col] = o0;
                *(float2*)&out[((size_t)b * S_LEN + row0 + 8) * D_MODEL + col] = o1;
            }
        }
    }
}

// =====================================================================
extern "C" void kernel_launch(void* const* d_in, const int* in_sizes, int n_in,
                              void* d_out, int out_size)
{
    const float* x  = (const float*)d_in[0];
    const float* Wq = (const float*)d_in[1];
    const float* bq = (const float*)d_in[2];
    const float* Wk = (const float*)d_in[3];
    const float* bk = (const float*)d_in[4];
    const float* Wv = (const float*)d_in[5];
    const float* bv = (const float*)d_in[6];
    float* out = (float*)d_out;

    cudaFuncSetAttribute(qkv_mma, cudaFuncAttributeMaxDynamicSharedMemorySize, QKV_SMEM);
    cudaFuncSetAttribute(attn_fused, cudaFuncAttributeMaxDynamicSharedMemorySize, FU_SMEM);

    pack_x<<<(MT_ALL * KT_ALL * 32) / 256, 256>>>(x);
    pack_w<<<dim3((NT_ALL * KT_ALL * 32) / 256, 3), 256>>>(Wq, Wk, Wv);

    qkv_mma<<<dim3(D_MODEL / 128, M_ALL / 128, 3), 256, QKV_SMEM>>>(bq, bk, bv);

    attn_fused<<<dim3(NTILES, B_BATCH), 256, FU_SMEM>>>(out);
}

// round 17
// speedup vs baseline: 6.5124x; 1.6244x over previous
#include <cuda_runtime.h>
#include <cuda_fp16.h>
#include <math.h>
#include <stdint.h>

#define B_BATCH 4
#define S_LEN   4096
#define D_MODEL 512
#define HALF_W  128
#define BAND    320
#define NTILES  (S_LEN / 64)

#define M_ALL   (B_BATCH * S_LEN)          // 16384 rows
#define MT_ALL  (M_ALL / 16)               // 1024 m-tiles (16 rows)
#define JT8_ALL (M_ALL / 8)                // 2048 key-tiles of 8
#define JT16_ALL (M_ALL / 16)              // 1024 key-tiles of 16
#define KT16    (D_MODEL / 16)             // 32 k-tiles of 16
#define NT8     (D_MODEL / 8)              // 64 n-tiles of 8

// ---------------- device scratch (fp16 fragment-packed, uint32 units) ----
__device__ unsigned g_Xp[(size_t)MT_ALL * KT16 * 32 * 4];    // a-frag x
__device__ unsigned g_Wp[3][(size_t)NT8 * KT16 * 32 * 2];    // b-frag W
__device__ unsigned g_Qp[(size_t)MT_ALL * KT16 * 32 * 4];    // a-frag Q (pre-scaled)
__device__ unsigned g_Kp[(size_t)JT8_ALL * KT16 * 32 * 2];   // b-frag K (n=key, k=d)
__device__ unsigned g_Vp[(size_t)JT16_ALL * NT8 * 32 * 2];   // b-frag V (k=key, n=d)

// ---------------- helpers ----------------
__device__ __forceinline__ unsigned h2u(float lo, float hi) {
    __half2 h = __floats2half2_rn(lo, hi);
    return *(unsigned*)&h;
}

__device__ __forceinline__ void mma_fp16(float c[4],
                                         unsigned a0, unsigned a1, unsigned a2, unsigned a3,
                                         unsigned b0, unsigned b1) {
    asm volatile(
        "mma.sync.aligned.m16n8k16.row.col.f32.f16.f16.f32 "
        "{%0,%1,%2,%3}, {%4,%5,%6,%7}, {%8,%9}, {%0,%1,%2,%3};\n"
        : "+f"(c[0]), "+f"(c[1]), "+f"(c[2]), "+f"(c[3])
        : "r"(a0), "r"(a1), "r"(a2), "r"(a3), "r"(b0), "r"(b1));
}

__device__ __forceinline__ void cp16(void* dst_smem, const void* src, int szbytes) {
    unsigned d = (unsigned)__cvta_generic_to_shared(dst_smem);
    asm volatile("cp.async.cg.shared.global [%0], [%1], 16, %2;\n"
                 :: "r"(d), "l"(src), "r"(szbytes));
}
__device__ __forceinline__ void cp_commit() {
    asm volatile("cp.async.commit_group;\n");
}
template <int N> __device__ __forceinline__ void cp_wait() {
    asm volatile("cp.async.wait_group %0;\n" :: "n"(N));
}

// =====================================================================
// Kernel 0a: pack x into fp16 a-frag order.
// chunk c = (mt, kt, lane); lane holds A[g|g+8][2tg,2tg+1 | +8] (8 halves)
// =====================================================================
__global__ __launch_bounds__(256) void pack_x(const float* __restrict__ x)
{
    int c = blockIdx.x * blockDim.x + threadIdx.x;
    const int total = MT_ALL * KT16 * 32;
    if (c >= total) return;
    int lane = c & 31;
    int kt = (c >> 5) & (KT16 - 1);
    int mt = c >> 10;
    int g = lane >> 2, tg = lane & 3;
    const float* r0 = x + (size_t)(mt * 16 + g) * D_MODEL + kt * 16 + 2 * tg;
    const float* r1 = r0 + 8 * D_MODEL;
    uint4 u;
    u.x = h2u(r0[0], r0[1]);
    u.y = h2u(r1[0], r1[1]);
    u.z = h2u(r0[8], r0[9]);
    u.w = h2u(r1[8], r1[9]);
    *(uint4*)&g_Xp[(size_t)c * 4] = u;
}

// =====================================================================
// Kernel 0b: pack W into fp16 b-frag order.
// chunk c = (nt, kt, lane); b0 = {W[2tg][g], W[2tg+1][g]}, b1 = k+8
// =====================================================================
__global__ __launch_bounds__(256) void pack_w(
    const float* __restrict__ Wq, const float* __restrict__ Wk, const float* __restrict__ Wv)
{
    const float* src = (blockIdx.y == 0) ? Wq : (blockIdx.y == 1) ? Wk : Wv;
    unsigned* dst = g_Wp[blockIdx.y];
    int c = blockIdx.x * blockDim.x + threadIdx.x;
    const int total = NT8 * KT16 * 32;
    if (c >= total) return;
    int lane = c & 31;
    int kt = (c >> 5) & (KT16 - 1);
    int nt = c >> 10;
    int g = lane >> 2, tg = lane & 3;
    const float* p = src + (size_t)(kt * 16 + 2 * tg) * D_MODEL + nt * 8 + g;
    uint2 o;
    o.x = h2u(p[0], p[D_MODEL]);
    o.y = h2u(p[8 * D_MODEL], p[9 * D_MODEL]);
    *(uint2*)&dst[(size_t)c * 2] = o;
}

// =====================================================================
// Kernel 1: QKV projection, fp16 MMA, fragment-packed in AND out.
// Block 128x128, BK=32 (2 k16-tiles/stage), 256 thr (2m x 4n warps).
// =====================================================================
#define QKV_AS  2048
#define QKV_BS  2048
#define QKV_SMEM 33792   // max(pipeline 32768, epilogue 64*132*4)

__global__ __launch_bounds__(256, 2) void qkv_mma(
    const float* __restrict__ bq, const float* __restrict__ bk, const float* __restrict__ bv)
{
    extern __shared__ unsigned smem[];
    unsigned* sA = smem;                  // [2][8mt][2kt][32][4]
    unsigned* sB = smem + 2 * QKV_AS;     // [2][16nt][2kt][32][2]

    const int z = blockIdx.z;
    const unsigned* Wp = g_Wp[z];
    const float* bias = (z == 0) ? bq : (z == 1) ? bk : bv;
    const float oscale = (z == 0) ? 0.044194173824159216f : 1.0f;

    const int m0 = blockIdx.y * 128;
    const int n0 = blockIdx.x * 128;
    const int mt0 = m0 >> 4;
    const int tid = threadIdx.x;
    const int warp = tid >> 5;
    const int lane = tid & 31;
    const int warp_m = warp >> 2;
    const int warp_n = warp & 3;
    const int g  = lane >> 2;
    const int tg = lane & 3;

    float acc[4][4][4];
#pragma unroll
    for (int mf = 0; mf < 4; mf++)
#pragma unroll
        for (int nf = 0; nf < 4; nf++)
#pragma unroll
            for (int c = 0; c < 4; c++) acc[mf][nf][c] = 0.f;

    const int T = KT16 / 2;   // 16 stages

    auto load_stage = [&](int s) {
        unsigned* dA = sA + (s & 1) * QKV_AS;
        unsigned* dB = sB + (s & 1) * QKV_BS;
        const int ktb = s * 2;
        // A: 512 chunks16B (mt8 x kt2 x lane32), 2/thread
#pragma unroll
        for (int i = 0; i < 2; i++) {
            int c = i * 256 + tid;
            int mt = c >> 6;
            int kt = (c >> 5) & 1;
            int ln = c & 31;
            cp16(&dA[((mt * 2 + kt) * 32 + ln) * 4],
                 &g_Xp[(((size_t)(mt0 + mt) * KT16 + ktb + kt) * 32 + ln) * 4], 16);
        }
        // B: 512 chunks16B (nt16 x kt2 x pr16), 2/thread
#pragma unroll
        for (int i = 0; i < 2; i++) {
            int c = i * 256 + tid;
            int nt = c >> 5;
            int kt = (c >> 4) & 1;
            int pr = c & 15;
            cp16(&dB[((nt * 2 + kt) * 32 + pr * 2) * 2],
                 &Wp[((((size_t)(n0 >> 3) + nt) * KT16 + ktb + kt) * 32 + pr * 2) * 2], 16);
        }
        cp_commit();
    };

    load_stage(0);

    for (int t = 0; t < T; t++) {
        if (t + 1 < T) {
            load_stage(t + 1);
            cp_wait<1>();
        } else {
            cp_wait<0>();
        }
        __syncthreads();

        const unsigned* cA = sA + (t & 1) * QKV_AS;
        const unsigned* cB = sB + (t & 1) * QKV_BS;

#pragma unroll
        for (int kt = 0; kt < 2; kt++) {
            uint4 a[4];
            uint2 b[4];
#pragma unroll
            for (int mf = 0; mf < 4; mf++)
                a[mf] = *(const uint4*)&cA[(((warp_m * 4 + mf) * 2 + kt) * 32 + lane) * 4];
#pragma unroll
            for (int nf = 0; nf < 4; nf++)
                b[nf] = *(const uint2*)&cB[(((warp_n * 4 + nf) * 2 + kt) * 32 + lane) * 2];
#pragma unroll
            for (int mf = 0; mf < 4; mf++)
#pragma unroll
                for (int nf = 0; nf < 4; nf++)
                    mma_fp16(acc[mf][nf], a[mf].x, a[mf].y, a[mf].z, a[mf].w,
                             b[nf].x, b[nf].y);
        }
        __syncthreads();
    }

    // ---- epilogue: stage half-tiles (64x132 fp32) through smem, emit packed ----
    float* st = (float*)smem;
    for (int p = 0; p < 2; p++) {
        __syncthreads();
        if (warp_m == p) {
#pragma unroll
            for (int mf = 0; mf < 4; mf++) {
                int rl = mf * 16 + g;
#pragma unroll
                for (int nf = 0; nf < 4; nf++) {
                    int cl = warp_n * 32 + nf * 8 + 2 * tg;
                    float2 bv = *(const float2*)&bias[n0 + cl];
                    st[rl * 132 + cl]           = (acc[mf][nf][0] + bv.x) * oscale;
                    st[rl * 132 + cl + 1]       = (acc[mf][nf][1] + bv.y) * oscale;
                    st[(rl + 8) * 132 + cl]     = (acc[mf][nf][2] + bv.x) * oscale;
                    st[(rl + 8) * 132 + cl + 1] = (acc[mf][nf][3] + bv.y) * oscale;
                }
            }
        }
        __syncthreads();

        const int rowbase = m0 + p * 64;
        if (z == 0) {
            // Q a-frag: 4mt x 8kt x 32 lanes = 1024 uint4 chunks, 4/thread
#pragma unroll
            for (int i = 0; i < 4; i++) {
                int c = i * 256 + tid;
                int mt = c >> 8;
                int kt = (c >> 5) & 7;
                int ln = c & 31;
                int lg = ln >> 2, lt = ln & 3;
                const float* r0 = &st[(mt * 16 + lg) * 132 + kt * 16 + 2 * lt];
                const float* r1 = r0 + 8 * 132;
                uint4 u;
                u.x = h2u(r0[0], r0[1]);
                u.y = h2u(r1[0], r1[1]);
                u.z = h2u(r0[8], r0[9]);
                u.w = h2u(r1[8], r1[9]);
                size_t mt_g = (size_t)(rowbase >> 4) + mt;
                size_t kt_g = (size_t)(n0 >> 4) + kt;
                *(uint4*)&g_Qp[((mt_g * KT16 + kt_g) * 32 + ln) * 4] = u;
            }
        } else if (z == 1) {
            // K b-frag: 8jt x 8kt x 32 lanes = 2048 uint2 chunks, 8/thread
#pragma unroll
            for (int i = 0; i < 8; i++) {
                int c = i * 256 + tid;
                int jt = c >> 8;
                int kt = (c >> 5) & 7;
                int ln = c & 31;
                int lg = ln >> 2, lt = ln & 3;
                const float* r = &st[(jt * 8 + lg) * 132 + kt * 16 + 2 * lt];
                uint2 u;
                u.x = h2u(r[0], r[1]);
                u.y = h2u(r[8], r[9]);
                size_t jt_g = (size_t)(rowbase >> 3) + jt;
                size_t kt_g = (size_t)(n0 >> 4) + kt;
                *(uint2*)&g_Kp[((jt_g * KT16 + kt_g) * 32 + ln) * 2] = u;
            }
        } else {
            // V b-frag: 4jt16 x 16nt x 32 lanes = 2048 uint2 chunks, 8/thread
#pragma unroll
            for (int i = 0; i < 8; i++) {
                int c = i * 256 + tid;
                int jt = c >> 9;
                int nt = (c >> 5) & 15;
                int ln = c & 31;
                int lg = ln >> 2, lt = ln & 3;
                const float* base = &st[nt * 8 + lg];
                uint2 u;
                u.x = h2u(base[(jt * 16 + 2 * lt) * 132],     base[(jt * 16 + 2 * lt + 1) * 132]);
                u.y = h2u(base[(jt * 16 + 2 * lt + 8) * 132], base[(jt * 16 + 2 * lt + 9) * 132]);
                size_t jt_g = (size_t)(rowbase >> 4) + jt;
                size_t nt_g = (size_t)(n0 >> 3) + nt;
                *(uint2*)&g_Vp[((jt_g * NT8 + nt_g) * 32 + ln) * 2] = u;
            }
        }
    }
}

// =====================================================================
// Kernel 2: FUSED attention (fp16): scores + softmax -> P(smem fp16) -> O.
// Block = 64 queries x 320-key band x 512 cols.
// Phase 1: BK=32 (2 k16/stage), 16 stages. P smem [64][328] halves.
// Phase 2: V stages of 32 keys, 10 per n-chunk, 4 n-chunks of 128.
// =====================================================================
#define F_QS 1024                   // uints per Q stage
#define F_KS 5120                   // uints per K stage
#define F_QK (2 * F_QS + 2 * F_KS)  // 12288 uints
#define F_PS_H 328                  // P row stride in halves
#define F_VS 2048                   // uints per V stage (32 keys x 128 cols)
#define FU_SMEM ((F_QK + 2 * F_VS + 512) * 4)   // 67584 B

__global__ __launch_bounds__(256, 2) void attn_fused(float* __restrict__ out)
{
    extern __shared__ unsigned smem[];
    unsigned* sQ = smem;                   // [2][F_QS] (phase 1)
    unsigned* sK = smem + 2 * F_QS;        // [2][F_KS] (phase 1)
    __half*   sPh = (__half*)smem;         // [64][328] (overlays QK after phase 1)
    unsigned* sV = smem + F_QK;            // [2][F_VS]
    float* redm = (float*)(smem + F_QK + 2 * F_VS);   // [64][4]
    float* reds = redm + 64 * 4;                       // [64][4]

    const int t0 = blockIdx.x * 64;
    const int b  = blockIdx.y;
    const int mt0 = b * 256 + (t0 >> 4);
    const int jtb8  = (t0 - HALF_W) / 8;   // first band key-tile (8)
    const int jtb16 = (t0 - HALF_W) / 16;  // first band key-tile (16)

    const int tid = threadIdx.x;
    const int warp = tid >> 5;
    const int lane = tid & 31;
    const int warp_m = warp >> 2;
    const int warp_n = warp & 3;
    const int g  = lane >> 2;
    const int tg = lane & 3;

    // ---------------- phase 1: scores ----------------
    float acc[2][10][4];
#pragma unroll
    for (int mf = 0; mf < 2; mf++)
#pragma unroll
        for (int nf = 0; nf < 10; nf++)
#pragma unroll
            for (int c = 0; c < 4; c++) acc[mf][nf][c] = 0.f;

    const int T1 = KT16 / 2;   // 16 stages

    auto load_qk = [&](int s) {
        unsigned* dQ = sQ + (s & 1) * F_QS;
        unsigned* dK = sK + (s & 1) * F_KS;
        const int ktb = s * 2;
        {
            int c = tid;                // 256 chunks: mt4 x kt2 x lane32
            int mt = c >> 6;
            int kt = (c >> 5) & 1;
            int ln = c & 31;
            cp16(&dQ[((mt * 2 + kt) * 32 + ln) * 4],
                 &g_Qp[(((size_t)(mt0 + mt) * KT16 + ktb + kt) * 32 + ln) * 4], 16);
        }
#pragma unroll
        for (int i = 0; i < 5; i++) {   // 1280 chunks: jt40 x kt2 x pr16
            int c = i * 256 + tid;
            int jt = c >> 5;
            int kt = (c >> 4) & 1;
            int pr = c & 15;
            int jl = jtb8 + jt;
            jl = max(0, min(511, jl));
            size_t jt_g = (size_t)b * 512 + jl;
            cp16(&dK[((jt * 2 + kt) * 32 + pr * 2) * 2],
                 &g_Kp[((jt_g * KT16 + ktb + kt) * 32 + pr * 2) * 2], 16);
        }
        cp_commit();
    };

    load_qk(0);

    for (int t = 0; t < T1; t++) {
        if (t + 1 < T1) {
            load_qk(t + 1);
            cp_wait<1>();
        } else {
            cp_wait<0>();
        }
        __syncthreads();

        const unsigned* cQ = sQ + (t & 1) * F_QS;
        const unsigned* cK = sK + (t & 1) * F_KS;

#pragma unroll
        for (int kt = 0; kt < 2; kt++) {
            uint4 a[2];
            uint2 bfr[10];
#pragma unroll
            for (int mf = 0; mf < 2; mf++)
                a[mf] = *(const uint4*)&cQ[(((warp_m * 2 + mf) * 2 + kt) * 32 + lane) * 4];
#pragma unroll
            for (int nf = 0; nf < 10; nf++)
                bfr[nf] = *(const uint2*)&cK[(((warp_n * 10 + nf) * 2 + kt) * 32 + lane) * 2];
#pragma unroll
            for (int mf = 0; mf < 2; mf++)
#pragma unroll
                for (int nf = 0; nf < 10; nf++)
                    mma_fp16(acc[mf][nf], a[mf].x, a[mf].y, a[mf].z, a[mf].w,
                             bfr[nf].x, bfr[nf].y);
        }
        __syncthreads();
    }

    // V flat-stage f = nc*10 + s: 32 keys x 128 cols per stage
    auto load_v = [&](int f) {
        int nc = f / 10;
        int s  = f - nc * 10;
        unsigned* dV = sV + (f & 1) * F_VS;
#pragma unroll
        for (int i = 0; i < 2; i++) {   // 512 chunks: kt2 x nt16 x pr16
            int c = i * 256 + tid;
            int kt = c >> 8;
            int nt = (c >> 4) & 15;
            int pr = c & 15;
            int jl = jtb16 + 2 * s + kt;
            jl = max(0, min(255, jl));  // clamp; P==0 for OOB keys
            size_t jt_g = (size_t)b * 256 + jl;
            cp16(&dV[((kt * 16 + nt) * 32 + pr * 2) * 2],
                 &g_Vp[((jt_g * NT8 + nc * 16 + nt) * 32 + pr * 2) * 2], 16);
        }
        cp_commit();
    };

    load_v(0);   // prefetch during softmax (disjoint smem region)

    // ---------------- masking + softmax ----------------
    float rmax[2][2];
#pragma unroll
    for (int mf = 0; mf < 2; mf++)
#pragma unroll
        for (int h = 0; h < 2; h++) rmax[mf][h] = -INFINITY;

#pragma unroll
    for (int mf = 0; mf < 2; mf++)
#pragma unroll
        for (int h = 0; h < 2; h++) {
            const int r = warp_m * 32 + mf * 16 + g + h * 8;
#pragma unroll
            for (int nf = 0; nf < 10; nf++)
#pragma unroll
                for (int cc = 0; cc < 2; cc++) {
                    int c = warp_n * 80 + nf * 8 + 2 * tg + cc;
                    int jg = t0 - HALF_W + c;
                    bool valid = (c >= r) && (c <= r + 2 * HALF_W) && (jg >= 0) && (jg < S_LEN);
                    float v = valid ? acc[mf][nf][h * 2 + cc] : -INFINITY;
                    acc[mf][nf][h * 2 + cc] = v;
                    rmax[mf][h] = fmaxf(rmax[mf][h], v);
                }
        }
#pragma unroll
    for (int mf = 0; mf < 2; mf++)
#pragma unroll
        for (int h = 0; h < 2; h++) {
            rmax[mf][h] = fmaxf(rmax[mf][h], __shfl_xor_sync(0xffffffffu, rmax[mf][h], 1));
            rmax[mf][h] = fmaxf(rmax[mf][h], __shfl_xor_sync(0xffffffffu, rmax[mf][h], 2));
        }
    if (tg == 0)
#pragma unroll
        for (int mf = 0; mf < 2; mf++)
#pragma unroll
            for (int h = 0; h < 2; h++)
                redm[(warp_m * 32 + mf * 16 + g + h * 8) * 4 + warp_n] = rmax[mf][h];
    __syncthreads();

    float gm[2][2];
#pragma unroll
    for (int mf = 0; mf < 2; mf++)
#pragma unroll
        for (int h = 0; h < 2; h++) {
            int r = warp_m * 32 + mf * 16 + g + h * 8;
            gm[mf][h] = fmaxf(fmaxf(redm[r * 4 + 0], redm[r * 4 + 1]),
                              fmaxf(redm[r * 4 + 2], redm[r * 4 + 3]));
        }

    float rsum[2][2] = {{0.f, 0.f}, {0.f, 0.f}};
#pragma unroll
    for (int mf = 0; mf < 2; mf++)
#pragma unroll
        for (int h = 0; h < 2; h++)
#pragma unroll
            for (int nf = 0; nf < 10; nf++)
#pragma unroll
                for (int cc = 0; cc < 2; cc++) {
                    float e = __expf(acc[mf][nf][h * 2 + cc] - gm[mf][h]);
                    acc[mf][nf][h * 2 + cc] = e;
                    rsum[mf][h] += e;
                }
#pragma unroll
    for (int mf = 0; mf < 2; mf++)
#pragma unroll
        for (int h = 0; h < 2; h++) {
            rsum[mf][h] += __shfl_xor_sync(0xffffffffu, rsum[mf][h], 1);
            rsum[mf][h] += __shfl_xor_sync(0xffffffffu, rsum[mf][h], 2);
        }
    if (tg == 0)
#pragma unroll
        for (int mf = 0; mf < 2; mf++)
#pragma unroll
            for (int h = 0; h < 2; h++)
                reds[(warp_m * 32 + mf * 16 + g + h * 8) * 4 + warp_n] = rsum[mf][h];
    __syncthreads();

    // P -> smem fp16 [64][328]
#pragma unroll
    for (int mf = 0; mf < 2; mf++)
#pragma unroll
        for (int h = 0; h < 2; h++) {
            int r = warp_m * 32 + mf * 16 + g + h * 8;
            float s = reds[r * 4 + 0] + reds[r * 4 + 1] + reds[r * 4 + 2] + reds[r * 4 + 3];
            float inv = 1.0f / s;
#pragma unroll
            for (int nf = 0; nf < 10; nf++) {
                int c = warp_n * 80 + nf * 8 + 2 * tg;
                *(unsigned*)&sPh[r * F_PS_H + c] =
                    h2u(acc[mf][nf][h * 2 + 0] * inv, acc[mf][nf][h * 2 + 1] * inv);
            }
        }
    __syncthreads();

    // ---------------- phase 2: O = P @ V (4 n-chunks of 128) ----------------
    for (int nc = 0; nc < 4; nc++) {
        float oacc[2][4][4];
#pragma unroll
        for (int mf = 0; mf < 2; mf++)
#pragma unroll
            for (int nf = 0; nf < 4; nf++)
#pragma unroll
                for (int c = 0; c < 4; c++) oacc[mf][nf][c] = 0.f;

        for (int t = 0; t < 10; t++) {
            int f = nc * 10 + t;
            if (f + 1 < 40) {
                load_v(f + 1);
                cp_wait<1>();
            } else {
                cp_wait<0>();
            }
            __syncthreads();

            const unsigned* cV = sV + (f & 1) * F_VS;
            const int kb = t * 32;

#pragma unroll
            for (int kt = 0; kt < 2; kt++) {
                const int k0 = kb + kt * 16;
                unsigned a[2][4];
                uint2 bfr[4];
#pragma unroll
                for (int mf = 0; mf < 2; mf++) {
                    int m = warp_m * 32 + mf * 16 + g;
                    a[mf][0] = *(const unsigned*)&sPh[m * F_PS_H + k0 + 2 * tg];
                    a[mf][1] = *(const unsigned*)&sPh[(m + 8) * F_PS_H + k0 + 2 * tg];
                    a[mf][2] = *(const unsigned*)&sPh[m * F_PS_H + k0 + 2 * tg + 8];
                    a[mf][3] = *(const unsigned*)&sPh[(m + 8) * F_PS_H + k0 + 2 * tg + 8];
                }
#pragma unroll
                for (int nf = 0; nf < 4; nf++)
                    bfr[nf] = *(const uint2*)&cV[((kt * 16 + warp_n * 4 + nf) * 32 + lane) * 2];
#pragma unroll
                for (int mf = 0; mf < 2; mf++)
#pragma unroll
                    for (int nf = 0; nf < 4; nf++)
                        mma_fp16(oacc[mf][nf], a[mf][0], a[mf][1], a[mf][2], a[mf][3],
                                 bfr[nf].x, bfr[nf].y);
            }
            __syncthreads();
        }

#pragma unroll
        for (int mf = 0; mf < 2; mf++) {
            int row0 = t0 + warp_m * 32 + mf * 16 + g;
#pragma unroll
            for (int nf = 0; nf < 4; nf++) {
                int col = nc * 128 + warp_n * 32 + nf * 8 + 2 * tg;
                float2 o0, o1;
                o0.x = oacc[mf][nf][0]; o0.y = oacc[mf][nf][1];
                o1.x = oacc[mf][nf][2]; o1.y = oacc[mf][nf][3];
                *(float2*)&out[((size_t)b * S_LEN + row0) * D_MODEL + col] = o0;
                *(float2*)&out[((size_t)b * S_LEN + row0 + 8) * D_MODEL + col] = o1;
            }
        }
    }
}

// =====================================================================
extern "C" void kernel_launch(void* const* d_in, const int* in_sizes, int n_in,
                              void* d_out, int out_size)
{
    const float* x  = (const float*)d_in[0];
    const float* Wq = (const float*)d_in[1];
    const float* bq = (const float*)d_in[2];
    const float* Wk = (const float*)d_in[3];
    const float* bk = (const float*)d_in[4];
    const float* Wv = (const float*)d_in[5];
    const float* bv = (const float*)d_in[6];
    float* out = (float*)d_out;

    cudaFuncSetAttribute(qkv_mma, cudaFuncAttributeMaxDynamicSharedMemorySize, QKV_SMEM);
    cudaFuncSetAttribute(attn_fused, cudaFuncAttributeMaxDynamicSharedMemorySize, FU_SMEM);

    pack_x<<<(MT_ALL * KT16 * 32) / 256, 256>>>(x);
    pack_w<<<dim3((NT8 * KT16 * 32) / 256, 3), 256>>>(Wq, Wk, Wv);

    qkv_mma<<<dim3(D_MODEL / 128, M_ALL / 128, 3), 256, QKV_SMEM>>>(bq, bk, bv);

    attn_fused<<<dim3(NTILES, B_BATCH), 256, FU_SMEM>>>(out);
}